// round 12
// baseline (speedup 1.0000x reference)
#include <cuda_runtime.h>
#include <math.h>

#define N_NODES 4096
#define E_EDGES 131072
#define E_TOT   (E_EDGES + N_NODES)   /* 135168: raw edges + self loops */
#define INC     512
#define HIDC    64
#define NHEADS  8
#define OUTC    256
#define BETA_W  0.5f
#define NSLOPE  0.2f

/* ------------------ device scratch (no allocation allowed) ------------------ */
__device__ uint4 g_A4[((size_t)N_NODES * N_NODES) / 16];       /* dedup 0/1 adjacency bytes, 16.7MB */
#define g_A ((unsigned char*)g_A4)
__device__ __align__(16) float g_mw[(size_t)N_NODES * N_NODES]; /* motif weight, 67MB */
__device__ int g_src[E_EDGES], g_dst[E_EDGES];                  /* canonical int32 edge list */
__device__ int g_is64;
__device__ int g_cntOut[N_NODES], g_cntIn[N_NODES], g_cntGat[N_NODES];
__device__ int g_offOut[N_NODES + 1], g_offIn[N_NODES + 1], g_offGat[N_NODES + 1];
__device__ int g_curIn[N_NODES], g_curGat[N_NODES];
__device__ int g_listOut[E_TOT], g_listIn[E_TOT], g_listGat[E_TOT];
__device__ __align__(16) float g_H1[(size_t)N_NODES * INC];
__device__ __align__(16) float g_H2[(size_t)N_NODES * INC];
__device__ __align__(16) float g_G [(size_t)N_NODES * OUTC];
__device__ __align__(16) float g_R [(size_t)N_NODES * OUTC];
__device__ __align__(16) float g_aS[N_NODES * NHEADS], g_aD[N_NODES * NHEADS];
__device__ __align__(16) float g_mx1[N_NODES * NHEADS], g_mx2[N_NODES * NHEADS];
__device__ __align__(16) float g_s1 [N_NODES * NHEADS], g_s2 [N_NODES * NHEADS];
__device__ __align__(16) float g_eL[(size_t)E_TOT * NHEADS];
__device__ __align__(16) float g_eM[(size_t)E_TOT * NHEADS];

/* ------------------ edge-index dtype detection + canonicalization ------------
   JAX with x64 disabled silently stores "int64" edge_index as int32. Detect on
   device: interpret as int32 pairs — int64 data shows (value, 0) with value<N. */
__global__ void k_detect(const void* __restrict__ ei) {
    const unsigned* p = (const unsigned*)ei;
    int is64 = 1;
    for (int i = 0; i < 8; i++) {
        unsigned lo = p[2 * i], hi = p[2 * i + 1];
        if (hi != 0u || lo >= (unsigned)N_NODES) { is64 = 0; break; }
    }
    g_is64 = is64;
}
__global__ void k_convert(const void* __restrict__ ei) {
    int e = blockIdx.x * blockDim.x + threadIdx.x;
    if (e >= E_EDGES) return;
    int s, d;
    if (g_is64) {
        const long long* p = (const long long*)ei;
        s = (int)p[e]; d = (int)p[E_EDGES + e];
    } else {
        const int* p = (const int*)ei;
        s = p[e]; d = p[E_EDGES + e];
    }
    g_src[e] = s & (N_NODES - 1);   /* mask: never OOB even if detection wrong */
    g_dst[e] = d & (N_NODES - 1);
}

/* ------------------ clear kernels ------------------ */
__global__ void k_clearA() {
    size_t n16 = ((size_t)N_NODES * N_NODES) / 16;
    uint4 z = make_uint4(0, 0, 0, 0);
    for (size_t i = blockIdx.x * blockDim.x + threadIdx.x; i < n16;
         i += (size_t)gridDim.x * blockDim.x)
        g_A4[i] = z;
}
__global__ void k_clearCnt() {
    int i = blockIdx.x * blockDim.x + threadIdx.x;
    if (i >= N_NODES) return;
    g_cntOut[i] = 0; g_cntIn[i] = 0; g_cntGat[i] = 0;
    g_curIn[i] = 0;  g_curGat[i] = 0;
}

/* ------------------ helpers ------------------ */
__device__ __forceinline__ void atomicMaxF(float* addr, float v) {
    int* a = (int*)addr;
    int old = *a;
    while (__int_as_float(old) < v) {
        int prev = atomicCAS(a, old, __float_as_int(v));
        if (prev == old) break;
        old = prev;
    }
}
__device__ __forceinline__ float leaky(float v) { return v > 0.f ? v : NSLOPE * v; }

__device__ __forceinline__ void edge_sd(int e, int& s, int& d) {
    if (e < E_EDGES) { s = g_src[e]; d = g_dst[e]; }
    else             { s = d = e - E_EDGES; }
}

/* ------------------ graph construction ------------------ */
__global__ void k_fillAdj() {
    int e = blockIdx.x * blockDim.x + threadIdx.x;
    if (e >= E_TOT) return;
    int s, d; edge_sd(e, s, d);
    g_A[(size_t)s * N_NODES + d] = 1;
}

__global__ void k_rowCount() {
    int row = blockIdx.x;
    const unsigned char* r = g_A + (size_t)row * N_NODES;
    int p = 0;
    for (int j = threadIdx.x; j < N_NODES; j += blockDim.x) {
        if (r[j]) { p++; atomicAdd(&g_cntIn[j], 1); }
    }
    __shared__ int sh;
    if (threadIdx.x == 0) sh = 0;
    __syncthreads();
    atomicAdd(&sh, p);
    __syncthreads();
    if (threadIdx.x == 0) g_cntOut[row] = sh;
}

/* exclusive scan over 4096 ints, single block of 1024 threads */
__global__ void k_scan(int which) {
    const int* cnt = which == 0 ? g_cntOut : (which == 1 ? g_cntIn : g_cntGat);
    int*       off = which == 0 ? g_offOut : (which == 1 ? g_offIn : g_offGat);
    __shared__ int part[1024];
    int tid = threadIdx.x;
    int b = tid * 4;
    int c0 = cnt[b], c1 = cnt[b + 1], c2 = cnt[b + 2], c3 = cnt[b + 3];
    part[tid] = c0 + c1 + c2 + c3;
    __syncthreads();
    if (tid == 0) {
        int acc = 0;
        for (int i = 0; i < 1024; i++) { int t = part[i]; part[i] = acc; acc += t; }
        off[N_NODES] = acc;
    }
    __syncthreads();
    int p = part[tid];
    off[b] = p; off[b + 1] = p + c0; off[b + 2] = p + c0 + c1; off[b + 3] = p + c0 + c1 + c2;
}

/* one warp per row: compact dedup out-list, scatter in-list */
__global__ void k_buildLists() {
    int row  = (blockIdx.x * blockDim.x + threadIdx.x) >> 5;
    int lane = threadIdx.x & 31;
    if (row >= N_NODES) return;
    const unsigned char* r = g_A + (size_t)row * N_NODES;
    int cur = g_offOut[row];
    for (int j0 = 0; j0 < N_NODES; j0 += 32) {
        int v = r[j0 + lane];
        unsigned mask = __ballot_sync(0xffffffffu, v != 0);
        if (v) {
            int pos = cur + __popc(mask & ((1u << lane) - 1u));
            int col = j0 + lane;
            g_listOut[pos] = col;
            int ip = atomicAdd(&g_curIn[col], 1);
            g_listIn[g_offIn[col] + ip] = row;
        }
        cur += __popc(mask);
    }
}

__global__ void k_cntGat() {
    int e = blockIdx.x * blockDim.x + threadIdx.x;
    if (e >= E_TOT) return;
    int s, d; edge_sd(e, s, d);
    atomicAdd(&g_cntGat[d], 1);
}
__global__ void k_scatGat() {
    int e = blockIdx.x * blockDim.x + threadIdx.x;
    if (e >= E_TOT) return;
    int s, d; edge_sd(e, s, d);
    int pos = atomicAdd(&g_curGat[d], 1);
    g_listGat[g_offGat[d] + pos] = e;
}

/* ------------------ sparse motif: per-node B row + m3 gathers ------------------ */
__global__ void k_motif() {
    int s = blockIdx.x;
    __shared__ float Brow[N_NODES];
    __shared__ float sRS;
    for (int j = threadIdx.x; j < N_NODES; j += blockDim.x) Brow[j] = 0.f;
    if (threadIdx.x == 0) sRS = 0.f;
    __syncthreads();

    int ob = g_offOut[s], oe = g_offOut[s + 1];
    /* B[s,:] = sum_{k in out(s)} A[k,:]  (integer counts, exact in fp32) */
    for (int oi = ob + threadIdx.x; oi < oe; oi += blockDim.x) {
        int k = g_listOut[oi];
        int b = g_offOut[k], e2 = g_offOut[k + 1];
        for (int t = b; t < e2; t++) atomicAdd(&Brow[g_listOut[t]], 1.0f);
    }
    __syncthreads();

    /* rowsum(m3[s]) = sum_k B[s,k] * outdeg(k) */
    float p = 0.f;
    for (int j = threadIdx.x; j < N_NODES; j += blockDim.x)
        p += Brow[j] * (float)(g_offOut[j + 1] - g_offOut[j]);
    atomicAdd(&sRS, p);
    __syncthreads();
    float rs = sRS; if (rs < 1.f) rs = 1.f;

    /* m3[s,d] = sum_{k in in(d)} B[s,k]  for each dedup out-edge */
    int lane = threadIdx.x & 31, w = threadIdx.x >> 5;
    int nw = blockDim.x >> 5;
    for (int oi = ob + w; oi < oe; oi += nw) {
        int dd = g_listOut[oi];
        int b = g_offIn[dd], e2 = g_offIn[dd + 1];
        float sum = 0.f;
        for (int t = b + lane; t < e2; t += 32) sum += Brow[g_listIn[t]];
        #pragma unroll
        for (int o = 16; o; o >>= 1) sum += __shfl_down_sync(0xffffffffu, sum, o);
        if (lane == 0) g_mw[(size_t)s * N_NODES + dd] = sum / rs;
    }
}

/* ------------------ fp32 tiled GEMM: C[M,N] = A[M,K] * B[K,N] (row-major) ------
   IMPORTANT: A and C that live in __device__ global arrays are selected INSIDE
   device code (passing a __device__ symbol as a kernel arg from host passes the
   host shadow address — with ATS the kernel silently writes host memory). */
#define GBM 128
#define GBN 64
#define GBK 16
__global__ void k_gemm(const float* __restrict__ Aext, int outSel,
                       const float* __restrict__ B, int M, int N, int K) {
    const float* A = Aext ? Aext : g_H2;                       /* aSel: x or g_H2 */
    float* C = outSel == 0 ? g_H1 : (outSel == 1 ? g_G : g_R); /* device symbol */
    __shared__ __align__(16) float As[GBK][GBM];
    __shared__ __align__(16) float Bs[GBK][GBN];
    int tid = threadIdx.x;
    int tx = tid & 15, ty = tid >> 4;
    int bx = blockIdx.x, by = blockIdx.y;
    const float* Ab = A + (size_t)by * GBM * K;
    const float* Bb = B + bx * GBN;
    float acc[8][4];
    #pragma unroll
    for (int i = 0; i < 8; i++)
        #pragma unroll
        for (int j = 0; j < 4; j++) acc[i][j] = 0.f;

    int lam = tid >> 1;            /* A row in tile: 0..127 */
    int lak = (tid & 1) * 8;       /* A k offset: 0 or 8    */
    int lbk = tid >> 4;            /* B k row: 0..15        */
    int lbn = (tid & 15) * 4;      /* B n offset            */

    for (int k0 = 0; k0 < K; k0 += GBK) {
        float4 a0 = *(const float4*)(Ab + (size_t)lam * K + k0 + lak);
        float4 a1 = *(const float4*)(Ab + (size_t)lam * K + k0 + lak + 4);
        As[lak + 0][lam] = a0.x; As[lak + 1][lam] = a0.y;
        As[lak + 2][lam] = a0.z; As[lak + 3][lam] = a0.w;
        As[lak + 4][lam] = a1.x; As[lak + 5][lam] = a1.y;
        As[lak + 6][lam] = a1.z; As[lak + 7][lam] = a1.w;
        *(float4*)&Bs[lbk][lbn] = *(const float4*)(Bb + (size_t)(k0 + lbk) * N + lbn);
        __syncthreads();
        #pragma unroll
        for (int k = 0; k < GBK; k++) {
            float4 av0 = *(float4*)&As[k][ty * 8];
            float4 av1 = *(float4*)&As[k][ty * 8 + 4];
            float4 bv  = *(float4*)&Bs[k][tx * 4];
            float ar[8] = {av0.x, av0.y, av0.z, av0.w, av1.x, av1.y, av1.z, av1.w};
            float br[4] = {bv.x, bv.y, bv.z, bv.w};
            #pragma unroll
            for (int i = 0; i < 8; i++)
                #pragma unroll
                for (int j = 0; j < 4; j++) acc[i][j] += ar[i] * br[j];
        }
        __syncthreads();
    }
    #pragma unroll
    for (int i = 0; i < 8; i++) {
        float4 v = make_float4(acc[i][0], acc[i][1], acc[i][2], acc[i][3]);
        *(float4*)(C + (size_t)(by * GBM + ty * 8 + i) * N + bx * GBN + tx * 4) = v;
    }
}

/* ------------------ GAT pieces ------------------ */
__global__ void k_init(int n) {
    int i = blockIdx.x * blockDim.x + threadIdx.x;
    if (i >= n) return;
    g_mx1[i] = -INFINITY; g_mx2[i] = -INFINITY;
    g_s1[i] = 0.f; g_s2[i] = 0.f;
}

__global__ void k_nodeDots1(const float* __restrict__ as1, const float* __restrict__ ad1) {
    int idx = blockIdx.x * blockDim.x + threadIdx.x;
    if (idx >= N_NODES * NHEADS) return;
    int n = idx >> 3, h = idx & 7;
    const float* hr = g_H1 + (size_t)n * INC + h * HIDC;
    float ss = 0.f, sd = 0.f;
    #pragma unroll 8
    for (int c = 0; c < HIDC; c++) { float v = hr[c]; ss += v * as1[h * HIDC + c]; sd += v * ad1[h * HIDC + c]; }
    g_aS[idx] = ss; g_aD[idx] = sd;
}

__global__ void k_nodeDots2(const float* __restrict__ as2, const float* __restrict__ ad2) {
    int n = (blockIdx.x * blockDim.x + threadIdx.x) >> 5;
    int lane = threadIdx.x & 31;
    if (n >= N_NODES) return;
    float ss = 0.f, sd = 0.f;
    for (int c = lane; c < OUTC; c += 32) {
        float v = g_G[(size_t)n * OUTC + c];
        ss += v * as2[c]; sd += v * ad2[c];
    }
    #pragma unroll
    for (int o = 16; o; o >>= 1) {
        ss += __shfl_down_sync(0xffffffffu, ss, o);
        sd += __shfl_down_sync(0xffffffffu, sd, o);
    }
    if (lane == 0) { g_aS[n] = ss; g_aD[n] = sd; }
}

template <int H>
__global__ void k_edgeA() {
    int idx = blockIdx.x * blockDim.x + threadIdx.x;
    if (idx >= E_TOT * H) return;
    int e = idx / H, h = idx % H;
    int s, d; edge_sd(e, s, d);
    float ev = g_aS[s * H + h] + g_aD[d * H + h];
    float mw = g_mw[(size_t)s * N_NODES + d];
    float el = leaky(ev);
    float em = leaky(ev * mw);
    g_eL[idx] = el; g_eM[idx] = em;
    atomicMaxF(&g_mx1[d * H + h], el);
    atomicMaxF(&g_mx2[d * H + h], em);
}

template <int H>
__global__ void k_edgeB() {
    int idx = blockIdx.x * blockDim.x + threadIdx.x;
    if (idx >= E_TOT * H) return;
    int e = idx / H, h = idx % H;
    int s, d; edge_sd(e, s, d);
    float a1 = expf(g_eL[idx] - g_mx1[d * H + h]);
    float a2 = expf(g_eM[idx] - g_mx2[d * H + h]);
    g_eL[idx] = a1; g_eM[idx] = a2;
    atomicAdd(&g_s1[d * H + h], a1);
    atomicAdd(&g_s2[d * H + h], a2);
}

template <int H>
__global__ void k_edgeC() {
    int idx = blockIdx.x * blockDim.x + threadIdx.x;
    if (idx >= E_TOT * H) return;
    int e = idx / H, h = idx % H;
    int s, d; edge_sd(e, s, d);
    float al = BETA_W * g_eL[idx] / (g_s1[d * H + h] + 1e-16f)
             + (1.f - BETA_W) * g_eM[idx] / (g_s2[d * H + h] + 1e-16f);
    g_eL[idx] = al;   /* final alpha */
}

__global__ void k_agg1(const float* __restrict__ b1) {
    int d = blockIdx.x;
    int begin = g_offGat[d], end = g_offGat[d + 1];
    int hc0 = threadIdx.x, hc1 = threadIdx.x + 256;
    int h0 = hc0 >> 6, h1 = hc1 >> 6;
    float acc0 = 0.f, acc1 = 0.f;
    for (int t = begin; t < end; t++) {
        int e = g_listGat[t];
        int s = (e < E_EDGES) ? g_src[e] : (e - E_EDGES);
        float a0 = g_eL[(size_t)e * NHEADS + h0];
        float a1 = g_eL[(size_t)e * NHEADS + h1];
        const float* hr = g_H1 + (size_t)s * INC;
        acc0 += a0 * hr[hc0];
        acc1 += a1 * hr[hc1];
    }
    float v0 = acc0 + b1[hc0];
    float v1 = acc1 + b1[hc1];
    g_H2[(size_t)d * INC + hc0] = v0 > 0.f ? v0 : expm1f(v0);
    g_H2[(size_t)d * INC + hc1] = v1 > 0.f ? v1 : expm1f(v1);
}

__global__ void k_agg2(const float* __restrict__ b2, float* __restrict__ out) {
    int d = blockIdx.x;
    int begin = g_offGat[d], end = g_offGat[d + 1];
    int c = threadIdx.x;           /* 256 threads, 1 channel each */
    float acc = 0.f;
    for (int t = begin; t < end; t++) {
        int e = g_listGat[t];
        int s = (e < E_EDGES) ? g_src[e] : (e - E_EDGES);
        acc += g_eL[e] * g_G[(size_t)s * OUTC + c];
    }
    out[(size_t)d * OUTC + c] = acc + g_R[(size_t)d * OUTC + c] + b2[c];
}

/* ------------------ launch ------------------ */
#define CDIV(a, b) (((a) + (b) - 1) / (b))

extern "C" void kernel_launch(void* const* d_in, const int* in_sizes, int n_in,
                              void* d_out, int out_size) {
    const float* x     = (const float*)d_in[0];
    const void*  ei    = d_in[1];                 /* int32 or int64, auto-detected */
    const float* W1    = (const float*)d_in[2];
    const float* as1   = (const float*)d_in[3];
    const float* ad1   = (const float*)d_in[4];
    const float* b1    = (const float*)d_in[5];
    const float* W2    = (const float*)d_in[6];
    const float* as2   = (const float*)d_in[7];
    const float* ad2   = (const float*)d_in[8];
    const float* b2    = (const float*)d_in[9];
    const float* resW2 = (const float*)d_in[10];
    float*       out   = (float*)d_out;

    /* canonicalize edge list (dtype-safe) + clear scratch */
    k_detect<<<1, 1>>>(ei);
    k_convert<<<CDIV(E_EDGES, 256), 256>>>(ei);
    k_clearA<<<2048, 256>>>();
    k_clearCnt<<<CDIV(N_NODES, 256), 256>>>();

    /* graph structure */
    k_fillAdj<<<CDIV(E_TOT, 256), 256>>>();
    k_rowCount<<<N_NODES, 256>>>();
    k_scan<<<1, 1024>>>(0);
    k_scan<<<1, 1024>>>(1);
    k_buildLists<<<CDIV(N_NODES * 32, 256), 256>>>();
    k_cntGat<<<CDIV(E_TOT, 256), 256>>>();
    k_scan<<<1, 1024>>>(2);
    k_scatGat<<<CDIV(E_TOT, 256), 256>>>();

    /* sparse motif weights (shared by both layers) */
    k_motif<<<N_NODES, 256>>>();

    /* layer 1:  H1 = x @ W1   (Aext = x, out = g_H1) */
    k_gemm<<<dim3(INC / GBN, N_NODES / GBM), 256>>>(x, 0, W1, N_NODES, INC, INC);
    k_init<<<CDIV(N_NODES * NHEADS, 256), 256>>>(N_NODES * NHEADS);
    k_nodeDots1<<<CDIV(N_NODES * NHEADS, 256), 256>>>(as1, ad1);
    k_edgeA<NHEADS><<<CDIV(E_TOT * NHEADS, 256), 256>>>();
    k_edgeB<NHEADS><<<CDIV(E_TOT * NHEADS, 256), 256>>>();
    k_edgeC<NHEADS><<<CDIV(E_TOT * NHEADS, 256), 256>>>();
    k_agg1<<<N_NODES, 256>>>(b1);

    /* layer 2:  G = H2 @ W2,  R = H2 @ resW2   (Aext = nullptr -> g_H2) */
    k_gemm<<<dim3(OUTC / GBN, N_NODES / GBM), 256>>>(nullptr, 1, W2, N_NODES, OUTC, INC);
    k_gemm<<<dim3(OUTC / GBN, N_NODES / GBM), 256>>>(nullptr, 2, resW2, N_NODES, OUTC, INC);
    k_init<<<CDIV(N_NODES, 256), 256>>>(N_NODES);
    k_nodeDots2<<<CDIV(N_NODES * 32, 256), 256>>>(as2, ad2);
    k_edgeA<1><<<CDIV(E_TOT, 256), 256>>>();
    k_edgeB<1><<<CDIV(E_TOT, 256), 256>>>();
    k_edgeC<1><<<CDIV(E_TOT, 256), 256>>>();
    k_agg2<<<N_NODES, 256>>>(b2, out);
}

// round 14
// speedup vs baseline: 1.0284x; 1.0284x over previous
#include <cuda_runtime.h>
#include <math.h>

#define N_NODES 4096
#define E_EDGES 131072
#define E_TOT   (E_EDGES + N_NODES)   /* 135168: raw edges + self loops */
#define INC     512
#define HIDC    64
#define NHEADS  8
#define OUTC    256
#define BETA_W  0.5f
#define NSLOPE  0.2f

/* ------------------ device scratch (no allocation allowed) ------------------ */
__device__ uint4 g_A4[((size_t)N_NODES * N_NODES) / 16];       /* dedup 0/1 adjacency bytes */
#define g_A ((unsigned char*)g_A4)
__device__ __align__(16) float g_mw[(size_t)N_NODES * N_NODES]; /* motif weight (edge slots only) */
__device__ int g_src[E_EDGES], g_dst[E_EDGES];
__device__ int g_is64;
__device__ int g_cntOut[N_NODES], g_cntIn[N_NODES], g_cntGat[N_NODES];
__device__ int g_offOut[N_NODES + 1], g_offIn[N_NODES + 1], g_offGat[N_NODES + 1];
__device__ int g_curIn[N_NODES], g_curGat[N_NODES];
__device__ int g_listOut[E_TOT], g_listIn[E_TOT], g_listGat[E_TOT];
__device__ __align__(16) float g_H1[(size_t)N_NODES * INC];
__device__ __align__(16) float g_H2[(size_t)N_NODES * INC];
__device__ __align__(16) float g_G [(size_t)N_NODES * OUTC];
__device__ __align__(16) float g_R [(size_t)N_NODES * OUTC];
__device__ __align__(16) float g_aS[N_NODES * NHEADS], g_aD[N_NODES * NHEADS];
__device__ __align__(16) unsigned g_mx1[N_NODES * NHEADS], g_mx2[N_NODES * NHEADS];
__device__ __align__(16) float g_s1 [N_NODES * NHEADS], g_s2 [N_NODES * NHEADS];
__device__ __align__(16) float g_eL[(size_t)E_TOT * NHEADS];
__device__ __align__(16) float g_eM[(size_t)E_TOT * NHEADS];

/* order-preserving float<->uint for native atomicMax */
__device__ __forceinline__ unsigned encf(float f) {
    unsigned u = __float_as_uint(f);
    return (u & 0x80000000u) ? ~u : (u | 0x80000000u);
}
__device__ __forceinline__ float decf(unsigned e) {
    return (e & 0x80000000u) ? __uint_as_float(e ^ 0x80000000u) : __uint_as_float(~e);
}
#define ENC_NEG_INF 0x007FFFFFu   /* encf(-inf) */

/* packed fp32x2 ops (PTX-only; ptxas never auto-fuses FFMA2) */
#define FMA2(d, a, b) asm("fma.rn.f32x2 %0, %1, %2, %0;" : "+l"(d) : "l"(a), "l"(b))
#define PACKDUP(d, f) asm("mov.b64 %0, {%1, %1};" : "=l"(d) : "f"(f))
#define UNPK2(lo, hi, v) asm("mov.b64 {%0, %1}, %2;" : "=f"(lo), "=f"(hi) : "l"(v))

/* ------------------ edge-index dtype detect + canonicalize ------------------ */
__global__ void k_detect(const void* __restrict__ ei) {
    const unsigned* p = (const unsigned*)ei;
    int is64 = 1;
    for (int i = 0; i < 8; i++) {
        unsigned lo = p[2 * i], hi = p[2 * i + 1];
        if (hi != 0u || lo >= (unsigned)N_NODES) { is64 = 0; break; }
    }
    g_is64 = is64;
}
__global__ void k_convert(const void* __restrict__ ei) {
    int e = blockIdx.x * blockDim.x + threadIdx.x;
    if (e >= E_EDGES) return;
    int s, d;
    if (g_is64) {
        const long long* p = (const long long*)ei;
        s = (int)p[e]; d = (int)p[E_EDGES + e];
    } else {
        const int* p = (const int*)ei;
        s = p[e]; d = p[E_EDGES + e];
    }
    s &= (N_NODES - 1); d &= (N_NODES - 1);
    g_src[e] = s; g_dst[e] = d;
    atomicAdd(&g_cntGat[d], 1);       /* raw-edge dst counts (self loops seeded =1) */
}

/* ------------------ clears ------------------ */
__global__ void k_clearA() {
    size_t n16 = ((size_t)N_NODES * N_NODES) / 16;
    uint4 z = make_uint4(0, 0, 0, 0);
    for (size_t i = blockIdx.x * blockDim.x + threadIdx.x; i < n16;
         i += (size_t)gridDim.x * blockDim.x)
        g_A4[i] = z;
}
__global__ void k_clearCnt() {
    int i = blockIdx.x * blockDim.x + threadIdx.x;
    if (i >= N_NODES) return;
    g_cntOut[i] = 0; g_cntIn[i] = 0; g_cntGat[i] = 1;  /* 1 = self loop */
    g_curIn[i] = 0;  g_curGat[i] = 0;
}

__device__ __forceinline__ float leaky(float v) { return v > 0.f ? v : NSLOPE * v; }
__device__ __forceinline__ void edge_sd(int e, int& s, int& d) {
    if (e < E_EDGES) { s = g_src[e]; d = g_dst[e]; }
    else             { s = d = e - E_EDGES; }
}

/* ------------------ graph construction ------------------ */
__global__ void k_fillAdj() {
    int e = blockIdx.x * blockDim.x + threadIdx.x;
    if (e >= E_TOT) return;
    int s, d; edge_sd(e, s, d);
    g_A[(size_t)s * N_NODES + d] = 1;
}

__global__ void k_rowCount() {
    int row = blockIdx.x;
    const unsigned char* r = g_A + (size_t)row * N_NODES;
    int p = 0;
    for (int j = threadIdx.x; j < N_NODES; j += blockDim.x) {
        if (r[j]) { p++; atomicAdd(&g_cntIn[j], 1); }
    }
    __shared__ int sh;
    if (threadIdx.x == 0) sh = 0;
    __syncthreads();
    atomicAdd(&sh, p);
    __syncthreads();
    if (threadIdx.x == 0) g_cntOut[row] = sh;
}

__global__ void k_scan(int which) {
    const int* cnt = which == 0 ? g_cntOut : (which == 1 ? g_cntIn : g_cntGat);
    int*       off = which == 0 ? g_offOut : (which == 1 ? g_offIn : g_offGat);
    __shared__ int part[1024];
    int tid = threadIdx.x;
    int b = tid * 4;
    int c0 = cnt[b], c1 = cnt[b + 1], c2 = cnt[b + 2], c3 = cnt[b + 3];
    part[tid] = c0 + c1 + c2 + c3;
    __syncthreads();
    if (tid == 0) {
        int acc = 0;
        for (int i = 0; i < 1024; i++) { int t = part[i]; part[i] = acc; acc += t; }
        off[N_NODES] = acc;
    }
    __syncthreads();
    int p = part[tid];
    off[b] = p; off[b + 1] = p + c0; off[b + 2] = p + c0 + c1; off[b + 3] = p + c0 + c1 + c2;
}

__global__ void k_buildLists() {
    int row  = (blockIdx.x * blockDim.x + threadIdx.x) >> 5;
    int lane = threadIdx.x & 31;
    if (row >= N_NODES) return;
    const unsigned char* r = g_A + (size_t)row * N_NODES;
    int cur = g_offOut[row];
    for (int j0 = 0; j0 < N_NODES; j0 += 32) {
        int v = r[j0 + lane];
        unsigned mask = __ballot_sync(0xffffffffu, v != 0);
        if (v) {
            int pos = cur + __popc(mask & ((1u << lane) - 1u));
            int col = j0 + lane;
            g_listOut[pos] = col;
            int ip = atomicAdd(&g_curIn[col], 1);
            g_listIn[g_offIn[col] + ip] = row;
        }
        cur += __popc(mask);
    }
}

__global__ void k_scatGat() {
    int e = blockIdx.x * blockDim.x + threadIdx.x;
    if (e >= E_TOT) return;
    int s, d; edge_sd(e, s, d);
    int pos = atomicAdd(&g_curGat[d], 1);
    g_listGat[g_offGat[d] + pos] = e;
}

/* ------------------ sparse motif ------------------ */
__global__ void k_motif() {
    int s = blockIdx.x;
    __shared__ float Brow[N_NODES];
    __shared__ float sRS;
    for (int j = threadIdx.x; j < N_NODES; j += blockDim.x) Brow[j] = 0.f;
    if (threadIdx.x == 0) sRS = 0.f;
    __syncthreads();

    int ob = g_offOut[s], oe = g_offOut[s + 1];
    for (int oi = ob + threadIdx.x; oi < oe; oi += blockDim.x) {
        int k = g_listOut[oi];
        int b = g_offOut[k], e2 = g_offOut[k + 1];
        for (int t = b; t < e2; t++) atomicAdd(&Brow[g_listOut[t]], 1.0f);
    }
    __syncthreads();

    float p = 0.f;
    for (int j = threadIdx.x; j < N_NODES; j += blockDim.x)
        p += Brow[j] * (float)(g_offOut[j + 1] - g_offOut[j]);
    atomicAdd(&sRS, p);
    __syncthreads();
    float rs = sRS; if (rs < 1.f) rs = 1.f;

    int lane = threadIdx.x & 31, w = threadIdx.x >> 5;
    int nw = blockDim.x >> 5;
    for (int oi = ob + w; oi < oe; oi += nw) {
        int dd = g_listOut[oi];
        int b = g_offIn[dd], e2 = g_offIn[dd + 1];
        float sum = 0.f;
        for (int t = b + lane; t < e2; t += 32) sum += Brow[g_listIn[t]];
        #pragma unroll
        for (int o = 16; o; o >>= 1) sum += __shfl_down_sync(0xffffffffu, sum, o);
        if (lane == 0) g_mw[(size_t)s * N_NODES + dd] = sum / rs;
    }
}

/* ------------------ f32x2 GEMM: 128x128 tile, 8x8/thread --------------------
   mode 0: C=g_H1[4096x512] = Aext[4096x512] @ B0
   mode 1: A=g_H2; bx<2: C=g_G = A@B0 ; bx>=2: C=g_R = A@B1  (N=256 each) */
__global__ void __launch_bounds__(256) k_gemm(const float* __restrict__ Aext, int mode,
                                              const float* __restrict__ B0,
                                              const float* __restrict__ B1, int K) {
    __shared__ __align__(16) float As[16][128];
    __shared__ __align__(16) float Bs[16][128];
    int tid = threadIdx.x;
    int bx = blockIdx.x, by = blockIdx.y;
    const float* A; const float* B; float* C; int N;
    if (mode == 0) { A = Aext; B = B0; C = g_H1; N = 512; }
    else {
        A = g_H2; N = 256;
        if (bx < 2) { B = B0; C = g_G; } else { B = B1; C = g_R; bx -= 2; }
    }
    int tx = tid & 15, ty = tid >> 4;
    int arow = tid >> 1, akoff = (tid & 1) * 8;
    int bk = tid >> 4, bnoff = (tid & 15) * 8;

    unsigned long long acc[4][8];
    #pragma unroll
    for (int i = 0; i < 4; i++)
        #pragma unroll
        for (int j = 0; j < 8; j++) acc[i][j] = 0ull;

    const float* Abase = A + (size_t)(by * 128 + arow) * K + akoff;
    const float* Bbase = B + (size_t)bk * N + bx * 128 + bnoff;

    for (int k0 = 0; k0 < K; k0 += 16) {
        float4 a0 = *(const float4*)(Abase + k0);
        float4 a1 = *(const float4*)(Abase + k0 + 4);
        As[akoff + 0][arow] = a0.x; As[akoff + 1][arow] = a0.y;
        As[akoff + 2][arow] = a0.z; As[akoff + 3][arow] = a0.w;
        As[akoff + 4][arow] = a1.x; As[akoff + 5][arow] = a1.y;
        As[akoff + 6][arow] = a1.z; As[akoff + 7][arow] = a1.w;
        const float* Bg = Bbase + (size_t)k0 * N;
        *(float4*)&Bs[bk][bnoff]     = *(const float4*)(Bg);
        *(float4*)&Bs[bk][bnoff + 4] = *(const float4*)(Bg + 4);
        __syncthreads();
        #pragma unroll
        for (int k = 0; k < 16; k++) {
            ulonglong2 aA = *(const ulonglong2*)&As[k][ty * 8];      /* (m0,m1)(m2,m3) */
            ulonglong2 aB = *(const ulonglong2*)&As[k][ty * 8 + 4];  /* (m4,m5)(m6,m7) */
            float4 bv0 = *(const float4*)&Bs[k][tx * 8];
            float4 bv1 = *(const float4*)&Bs[k][tx * 8 + 4];
            unsigned long long bb[8];
            PACKDUP(bb[0], bv0.x); PACKDUP(bb[1], bv0.y);
            PACKDUP(bb[2], bv0.z); PACKDUP(bb[3], bv0.w);
            PACKDUP(bb[4], bv1.x); PACKDUP(bb[5], bv1.y);
            PACKDUP(bb[6], bv1.z); PACKDUP(bb[7], bv1.w);
            unsigned long long aa0 = aA.x, aa1 = aA.y, aa2 = aB.x, aa3 = aB.y;
            #pragma unroll
            for (int j = 0; j < 8; j++) {
                FMA2(acc[0][j], aa0, bb[j]);
                FMA2(acc[1][j], aa1, bb[j]);
                FMA2(acc[2][j], aa2, bb[j]);
                FMA2(acc[3][j], aa3, bb[j]);
            }
        }
        __syncthreads();
    }
    /* epilogue: acc[ip][j] lo -> row ty*8+2ip, hi -> row ty*8+2ip+1 */
    #pragma unroll
    for (int ip = 0; ip < 4; ip++) {
        float lo[8], hi[8];
        #pragma unroll
        for (int j = 0; j < 8; j++) UNPK2(lo[j], hi[j], acc[ip][j]);
        size_t base0 = (size_t)(by * 128 + ty * 8 + 2 * ip) * N + bx * 128 + tx * 8;
        size_t base1 = base0 + N;
        *(float4*)(C + base0)     = make_float4(lo[0], lo[1], lo[2], lo[3]);
        *(float4*)(C + base0 + 4) = make_float4(lo[4], lo[5], lo[6], lo[7]);
        *(float4*)(C + base1)     = make_float4(hi[0], hi[1], hi[2], hi[3]);
        *(float4*)(C + base1 + 4) = make_float4(hi[4], hi[5], hi[6], hi[7]);
    }
}

/* ------------------ GAT pieces ------------------ */
__global__ void k_init(int n) {
    int i = blockIdx.x * blockDim.x + threadIdx.x;
    if (i >= n) return;
    g_mx1[i] = ENC_NEG_INF; g_mx2[i] = ENC_NEG_INF;
    g_s1[i] = 0.f; g_s2[i] = 0.f;
}

__global__ void k_nodeDots1(const float* __restrict__ as1, const float* __restrict__ ad1) {
    int idx = blockIdx.x * blockDim.x + threadIdx.x;
    if (idx >= N_NODES * NHEADS) return;
    int n = idx >> 3, h = idx & 7;
    const float* hr = g_H1 + (size_t)n * INC + h * HIDC;
    float ss = 0.f, sd = 0.f;
    #pragma unroll 8
    for (int c = 0; c < HIDC; c++) { float v = hr[c]; ss += v * as1[h * HIDC + c]; sd += v * ad1[h * HIDC + c]; }
    g_aS[idx] = ss; g_aD[idx] = sd;
}

__global__ void k_nodeDots2(const float* __restrict__ as2, const float* __restrict__ ad2) {
    int n = (blockIdx.x * blockDim.x + threadIdx.x) >> 5;
    int lane = threadIdx.x & 31;
    if (n >= N_NODES) return;
    float ss = 0.f, sd = 0.f;
    for (int c = lane; c < OUTC; c += 32) {
        float v = g_G[(size_t)n * OUTC + c];
        ss += v * as2[c]; sd += v * ad2[c];
    }
    #pragma unroll
    for (int o = 16; o; o >>= 1) {
        ss += __shfl_down_sync(0xffffffffu, ss, o);
        sd += __shfl_down_sync(0xffffffffu, sd, o);
    }
    if (lane == 0) { g_aS[n] = ss; g_aD[n] = sd; }
}

template <int H>
__global__ void k_edgeA() {
    int idx = blockIdx.x * blockDim.x + threadIdx.x;
    if (idx >= E_TOT * H) return;
    int e = idx / H, h = idx % H;
    int s, d; edge_sd(e, s, d);
    float ev = g_aS[s * H + h] + g_aD[d * H + h];
    float mw = g_mw[(size_t)s * N_NODES + d];
    float el = leaky(ev);
    float em = leaky(ev * mw);
    g_eL[idx] = el; g_eM[idx] = em;
    atomicMax(&g_mx1[d * H + h], encf(el));
    atomicMax(&g_mx2[d * H + h], encf(em));
}

template <int H>
__global__ void k_edgeB() {
    int idx = blockIdx.x * blockDim.x + threadIdx.x;
    if (idx >= E_TOT * H) return;
    int e = idx / H, h = idx % H;
    int s, d; edge_sd(e, s, d);
    float a1 = expf(g_eL[idx] - decf(g_mx1[d * H + h]));
    float a2 = expf(g_eM[idx] - decf(g_mx2[d * H + h]));
    g_eL[idx] = a1; g_eM[idx] = a2;
    atomicAdd(&g_s1[d * H + h], a1);
    atomicAdd(&g_s2[d * H + h], a2);
}

/* aggregation with inline alpha normalization (edgeC folded in) */
__global__ void k_agg1(const float* __restrict__ b1) {
    int d = blockIdx.x;
    __shared__ float inv1[NHEADS], inv2[NHEADS];
    if (threadIdx.x < NHEADS) {
        inv1[threadIdx.x] = BETA_W / (g_s1[d * NHEADS + threadIdx.x] + 1e-16f);
        inv2[threadIdx.x] = (1.f - BETA_W) / (g_s2[d * NHEADS + threadIdx.x] + 1e-16f);
    }
    __syncthreads();
    int begin = g_offGat[d], end = g_offGat[d + 1];
    int hc0 = threadIdx.x, hc1 = threadIdx.x + 256;
    int h0 = hc0 >> 6, h1 = hc1 >> 6;
    float i10 = inv1[h0], i20 = inv2[h0], i11 = inv1[h1], i21 = inv2[h1];
    float acc0 = 0.f, acc1 = 0.f;
    for (int t = begin; t < end; t++) {
        int e = g_listGat[t];
        int s = (e < E_EDGES) ? g_src[e] : (e - E_EDGES);
        size_t e8 = (size_t)e * NHEADS;
        float a0 = g_eL[e8 + h0] * i10 + g_eM[e8 + h0] * i20;
        float a1 = g_eL[e8 + h1] * i11 + g_eM[e8 + h1] * i21;
        const float* hr = g_H1 + (size_t)s * INC;
        acc0 += a0 * hr[hc0];
        acc1 += a1 * hr[hc1];
    }
    float v0 = acc0 + b1[hc0];
    float v1 = acc1 + b1[hc1];
    g_H2[(size_t)d * INC + hc0] = v0 > 0.f ? v0 : expm1f(v0);
    g_H2[(size_t)d * INC + hc1] = v1 > 0.f ? v1 : expm1f(v1);
}

__global__ void k_agg2(const float* __restrict__ b2, float* __restrict__ out) {
    int d = blockIdx.x;
    float i1 = BETA_W / (g_s1[d] + 1e-16f);
    float i2 = (1.f - BETA_W) / (g_s2[d] + 1e-16f);
    int begin = g_offGat[d], end = g_offGat[d + 1];
    int c = threadIdx.x;
    float acc = 0.f;
    for (int t = begin; t < end; t++) {
        int e = g_listGat[t];
        int s = (e < E_EDGES) ? g_src[e] : (e - E_EDGES);
        float al = g_eL[e] * i1 + g_eM[e] * i2;
        acc += al * g_G[(size_t)s * OUTC + c];
    }
    out[(size_t)d * OUTC + c] = acc + g_R[(size_t)d * OUTC + c] + b2[c];
}

/* ------------------ launch ------------------ */
#define CDIV(a, b) (((a) + (b) - 1) / (b))

extern "C" void kernel_launch(void* const* d_in, const int* in_sizes, int n_in,
                              void* d_out, int out_size) {
    const float* x     = (const float*)d_in[0];
    const void*  ei    = d_in[1];
    const float* W1    = (const float*)d_in[2];
    const float* as1   = (const float*)d_in[3];
    const float* ad1   = (const float*)d_in[4];
    const float* b1    = (const float*)d_in[5];
    const float* W2    = (const float*)d_in[6];
    const float* as2   = (const float*)d_in[7];
    const float* ad2   = (const float*)d_in[8];
    const float* b2    = (const float*)d_in[9];
    const float* resW2 = (const float*)d_in[10];
    float*       out   = (float*)d_out;

    k_detect<<<1, 1>>>(ei);
    k_clearCnt<<<CDIV(N_NODES, 256), 256>>>();
    k_convert<<<CDIV(E_EDGES, 256), 256>>>(ei);   /* also counts gat dsts */
    k_clearA<<<2048, 256>>>();

    k_fillAdj<<<CDIV(E_TOT, 256), 256>>>();
    k_rowCount<<<N_NODES, 256>>>();
    k_scan<<<1, 1024>>>(0);
    k_scan<<<1, 1024>>>(1);
    k_buildLists<<<CDIV(N_NODES * 32, 256), 256>>>();
    k_scan<<<1, 1024>>>(2);
    k_scatGat<<<CDIV(E_TOT, 256), 256>>>();

    k_motif<<<N_NODES, 256>>>();

    /* layer 1: H1 = x @ W1 */
    k_gemm<<<dim3(INC / 128, N_NODES / 128), 256>>>(x, 0, W1, nullptr, INC);
    k_init<<<CDIV(N_NODES * NHEADS, 256), 256>>>(N_NODES * NHEADS);
    k_nodeDots1<<<CDIV(N_NODES * NHEADS, 256), 256>>>(as1, ad1);
    k_edgeA<NHEADS><<<CDIV(E_TOT * NHEADS, 256), 256>>>();
    k_edgeB<NHEADS><<<CDIV(E_TOT * NHEADS, 256), 256>>>();
    k_agg1<<<N_NODES, 256>>>(b1);

    /* layer 2: G = H2@W2 and R = H2@resW2 in one fused launch */
    k_gemm<<<dim3(4, N_NODES / 128), 256>>>(nullptr, 1, W2, resW2, INC);
    k_init<<<CDIV(N_NODES, 256), 256>>>(N_NODES);
    k_nodeDots2<<<CDIV(N_NODES * 32, 256), 256>>>(as2, ad2);
    k_edgeA<1><<<CDIV(E_TOT, 256), 256>>>();
    k_edgeB<1><<<CDIV(E_TOT, 256), 256>>>();
    k_agg2<<<N_NODES, 256>>>(b2, out);
}

// round 15
// speedup vs baseline: 1.4118x; 1.3727x over previous
#include <cuda_runtime.h>
#include <math.h>

#define N_NODES 4096
#define E_EDGES 131072
#define E_TOT   (E_EDGES + N_NODES)
#define INC     512
#define HIDC    64
#define NHEADS  8
#define OUTC    256
#define BETA_W  0.5f
#define NSLOPE  0.2f
#define CAP1    320    /* max stashed in-degree, layer 1 */
#define CAP2    1024   /* max stashed in-degree, layer 2 */

/* ------------------ device scratch ------------------ */
__device__ uint4 g_A4[((size_t)N_NODES * N_NODES) / 16];
#define g_A ((unsigned char*)g_A4)
__device__ __align__(16) float g_mw[(size_t)N_NODES * N_NODES];
__device__ int g_src[E_EDGES], g_dst[E_EDGES];
__device__ int g_cntOut[N_NODES], g_cntIn[N_NODES], g_cntGat[N_NODES];
__device__ int g_offOut[N_NODES + 1], g_offIn[N_NODES + 1], g_offGat[N_NODES + 1];
__device__ int g_curIn[N_NODES], g_curGat[N_NODES];
__device__ int g_listOut[E_TOT], g_listIn[E_TOT], g_listGat[E_TOT];
__device__ __align__(16) float g_H1[(size_t)N_NODES * INC];
__device__ __align__(16) float g_H2[(size_t)N_NODES * INC];
__device__ __align__(16) float g_G [(size_t)N_NODES * OUTC];
__device__ __align__(16) float g_R [(size_t)N_NODES * OUTC];
__device__ __align__(16) float g_aS[N_NODES * NHEADS], g_aD[N_NODES * NHEADS];

/* packed fp32x2 ops */
#define FMA2(d, a, b) asm("fma.rn.f32x2 %0, %1, %2, %0;" : "+l"(d) : "l"(a), "l"(b))
#define PACKDUP(d, f) asm("mov.b64 %0, {%1, %1};" : "=l"(d) : "f"(f))
#define UNPK2(lo, hi, v) asm("mov.b64 {%0, %1}, %2;" : "=f"(lo), "=f"(hi) : "l"(v))

__device__ __forceinline__ float leaky(float v) { return v > 0.f ? v : NSLOPE * v; }
__device__ __forceinline__ int srcOf(int e) { return (e < E_EDGES) ? g_src[e] : (e - E_EDGES); }
__device__ __forceinline__ int popc4(uint4 v) {
    return __popc(v.x) + __popc(v.y) + __popc(v.z) + __popc(v.w);
}

/* ------------------ clear (A + counters) ------------------ */
__global__ void k_clearAll() {
    size_t n16 = ((size_t)N_NODES * N_NODES) / 16;
    uint4 z = make_uint4(0, 0, 0, 0);
    size_t gid = (size_t)blockIdx.x * blockDim.x + threadIdx.x;
    for (size_t i = gid; i < n16; i += (size_t)gridDim.x * blockDim.x) g_A4[i] = z;
    if (gid < N_NODES) {
        g_cntOut[gid] = 0; g_cntIn[gid] = 0; g_cntGat[gid] = 1;  /* 1 = self loop */
        g_curIn[gid] = 0;  g_curGat[gid] = 0;
    }
}

/* ------------------ canonicalize edges (dtype detect inline) ------------------ */
__global__ void k_convert(const void* __restrict__ ei) {
    int e = blockIdx.x * blockDim.x + threadIdx.x;
    if (e >= E_EDGES) return;
    const unsigned* p = (const unsigned*)ei;
    int is64 = 1;
    #pragma unroll
    for (int i = 0; i < 8; i++) {
        unsigned lo = p[2 * i], hi = p[2 * i + 1];
        if (hi != 0u || lo >= (unsigned)N_NODES) { is64 = 0; break; }
    }
    int s, d;
    if (is64) {
        const long long* q = (const long long*)ei;
        s = (int)q[e]; d = (int)q[E_EDGES + e];
    } else {
        const int* q = (const int*)ei;
        s = q[e]; d = q[E_EDGES + e];
    }
    s &= (N_NODES - 1); d &= (N_NODES - 1);
    g_src[e] = s; g_dst[e] = d;
    atomicAdd(&g_cntGat[d], 1);
}

/* ------------------ graph structure ------------------ */
__global__ void k_fillAdj() {
    int e = blockIdx.x * blockDim.x + threadIdx.x;
    if (e >= E_TOT) return;
    int s, d;
    if (e < E_EDGES) { s = g_src[e]; d = g_dst[e]; } else { s = d = e - E_EDGES; }
    g_A[(size_t)s * N_NODES + d] = 1;
}

/* vectorized: one block per row, one uint4 (16 cols) per thread */
__global__ void k_rowCount() {
    int row = blockIdx.x, tid = threadIdx.x;
    uint4 v = g_A4[(size_t)row * 256 + tid];
    int c = popc4(v);
    if (c) {
        unsigned ws[4] = {v.x, v.y, v.z, v.w};
        int base = tid * 16;
        #pragma unroll
        for (int k = 0; k < 4; k++) {
            unsigned ww = ws[k];
            while (ww) {
                int b = __ffs(ww) - 1; ww &= ww - 1;
                atomicAdd(&g_cntIn[base + k * 4 + (b >> 3)], 1);
            }
        }
    }
    /* block reduce c */
    __shared__ int sw[8];
    for (int o = 16; o; o >>= 1) c += __shfl_down_sync(0xffffffffu, c, o);
    if ((tid & 31) == 0) sw[tid >> 5] = c;
    __syncthreads();
    if (tid == 0) {
        int t = 0;
        #pragma unroll
        for (int i = 0; i < 8; i++) t += sw[i];
        g_cntOut[row] = t;
    }
}

/* 3 scans in one launch: blockIdx.x = which */
__global__ void k_scanAll() {
    int which = blockIdx.x;
    const int* cnt = which == 0 ? g_cntOut : (which == 1 ? g_cntIn : g_cntGat);
    int*       off = which == 0 ? g_offOut : (which == 1 ? g_offIn : g_offGat);
    __shared__ int part[1024];
    int tid = threadIdx.x;
    int b = tid * 4;
    int c0 = cnt[b], c1 = cnt[b + 1], c2 = cnt[b + 2], c3 = cnt[b + 3];
    part[tid] = c0 + c1 + c2 + c3;
    __syncthreads();
    if (tid == 0) {
        int acc = 0;
        for (int i = 0; i < 1024; i++) { int t = part[i]; part[i] = acc; acc += t; }
        off[N_NODES] = acc;
    }
    __syncthreads();
    int p = part[tid];
    off[b] = p; off[b + 1] = p + c0; off[b + 2] = p + c0 + c1; off[b + 3] = p + c0 + c1 + c2;
}

/* warp per row, uint4 loads */
__global__ void k_buildLists() {
    int row  = (blockIdx.x * blockDim.x + threadIdx.x) >> 5;
    int lane = threadIdx.x & 31;
    if (row >= N_NODES) return;
    const uint4* r4 = g_A4 + (size_t)row * 256;
    int cur = g_offOut[row];
    for (int j = 0; j < 256; j += 32) {
        uint4 v = r4[j + lane];
        int c = popc4(v);
        int inc = c;
        #pragma unroll
        for (int o = 1; o < 32; o <<= 1) {
            int n = __shfl_up_sync(0xffffffffu, inc, o);
            if (lane >= o) inc += n;
        }
        int pos = cur + inc - c;
        if (c) {
            unsigned ws[4] = {v.x, v.y, v.z, v.w};
            int base = (j + lane) * 16;
            #pragma unroll
            for (int k = 0; k < 4; k++) {
                unsigned ww = ws[k];
                while (ww) {
                    int b = __ffs(ww) - 1; ww &= ww - 1;
                    int col = base + k * 4 + (b >> 3);
                    g_listOut[pos++] = col;
                    int ip = atomicAdd(&g_curIn[col], 1);
                    g_listIn[g_offIn[col] + ip] = row;
                }
            }
        }
        cur += __shfl_sync(0xffffffffu, inc, 31);
    }
}

__global__ void k_scatGat() {
    int e = blockIdx.x * blockDim.x + threadIdx.x;
    if (e >= E_TOT) return;
    int d = (e < E_EDGES) ? g_dst[e] : (e - E_EDGES);
    int pos = atomicAdd(&g_curGat[d], 1);
    g_listGat[g_offGat[d] + pos] = e;
}

/* ------------------ sparse motif ------------------ */
__global__ void k_motif() {
    int s = blockIdx.x;
    __shared__ float Brow[N_NODES];
    __shared__ float sRS;
    for (int j = threadIdx.x; j < N_NODES; j += blockDim.x) Brow[j] = 0.f;
    if (threadIdx.x == 0) sRS = 0.f;
    __syncthreads();

    int ob = g_offOut[s], oe = g_offOut[s + 1];
    for (int oi = ob + threadIdx.x; oi < oe; oi += blockDim.x) {
        int k = g_listOut[oi];
        int b = g_offOut[k], e2 = g_offOut[k + 1];
        for (int t = b; t < e2; t++) atomicAdd(&Brow[g_listOut[t]], 1.0f);
    }
    __syncthreads();

    float p = 0.f;
    for (int j = threadIdx.x; j < N_NODES; j += blockDim.x)
        p += Brow[j] * (float)(g_offOut[j + 1] - g_offOut[j]);
    atomicAdd(&sRS, p);
    __syncthreads();
    float rs = sRS; if (rs < 1.f) rs = 1.f;

    int lane = threadIdx.x & 31, w = threadIdx.x >> 5;
    int nw = blockDim.x >> 5;
    for (int oi = ob + w; oi < oe; oi += nw) {
        int dd = g_listOut[oi];
        int b = g_offIn[dd], e2 = g_offIn[dd + 1];
        float sum = 0.f;
        for (int t = b + lane; t < e2; t += 32) sum += Brow[g_listIn[t]];
        #pragma unroll
        for (int o = 16; o; o >>= 1) sum += __shfl_down_sync(0xffffffffu, sum, o);
        if (lane == 0) g_mw[(size_t)s * N_NODES + dd] = sum / rs;
    }
}

/* ------------------ f32x2 GEMM (128x128 tile, 8x8/thread) ------------------ */
__global__ void __launch_bounds__(256) k_gemm(const float* __restrict__ Aext, int mode,
                                              const float* __restrict__ B0,
                                              const float* __restrict__ B1, int K) {
    __shared__ __align__(16) float As[16][128];
    __shared__ __align__(16) float Bs[16][128];
    int tid = threadIdx.x;
    int bx = blockIdx.x, by = blockIdx.y;
    const float* A; const float* B; float* C; int N;
    if (mode == 0) { A = Aext; B = B0; C = g_H1; N = 512; }
    else {
        A = g_H2; N = 256;
        if (bx < 2) { B = B0; C = g_G; } else { B = B1; C = g_R; bx -= 2; }
    }
    int tx = tid & 15, ty = tid >> 4;
    int arow = tid >> 1, akoff = (tid & 1) * 8;
    int bk = tid >> 4, bnoff = (tid & 15) * 8;

    unsigned long long acc[4][8];
    #pragma unroll
    for (int i = 0; i < 4; i++)
        #pragma unroll
        for (int j = 0; j < 8; j++) acc[i][j] = 0ull;

    const float* Abase = A + (size_t)(by * 128 + arow) * K + akoff;
    const float* Bbase = B + (size_t)bk * N + bx * 128 + bnoff;

    for (int k0 = 0; k0 < K; k0 += 16) {
        float4 a0 = *(const float4*)(Abase + k0);
        float4 a1 = *(const float4*)(Abase + k0 + 4);
        As[akoff + 0][arow] = a0.x; As[akoff + 1][arow] = a0.y;
        As[akoff + 2][arow] = a0.z; As[akoff + 3][arow] = a0.w;
        As[akoff + 4][arow] = a1.x; As[akoff + 5][arow] = a1.y;
        As[akoff + 6][arow] = a1.z; As[akoff + 7][arow] = a1.w;
        const float* Bg = Bbase + (size_t)k0 * N;
        *(float4*)&Bs[bk][bnoff]     = *(const float4*)(Bg);
        *(float4*)&Bs[bk][bnoff + 4] = *(const float4*)(Bg + 4);
        __syncthreads();
        #pragma unroll
        for (int k = 0; k < 16; k++) {
            ulonglong2 aA = *(const ulonglong2*)&As[k][ty * 8];
            ulonglong2 aB = *(const ulonglong2*)&As[k][ty * 8 + 4];
            float4 bv0 = *(const float4*)&Bs[k][tx * 8];
            float4 bv1 = *(const float4*)&Bs[k][tx * 8 + 4];
            unsigned long long bb[8];
            PACKDUP(bb[0], bv0.x); PACKDUP(bb[1], bv0.y);
            PACKDUP(bb[2], bv0.z); PACKDUP(bb[3], bv0.w);
            PACKDUP(bb[4], bv1.x); PACKDUP(bb[5], bv1.y);
            PACKDUP(bb[6], bv1.z); PACKDUP(bb[7], bv1.w);
            unsigned long long aa0 = aA.x, aa1 = aA.y, aa2 = aB.x, aa3 = aB.y;
            #pragma unroll
            for (int j = 0; j < 8; j++) {
                FMA2(acc[0][j], aa0, bb[j]);
                FMA2(acc[1][j], aa1, bb[j]);
                FMA2(acc[2][j], aa2, bb[j]);
                FMA2(acc[3][j], aa3, bb[j]);
            }
        }
        __syncthreads();
    }
    #pragma unroll
    for (int ip = 0; ip < 4; ip++) {
        float lo[8], hi[8];
        #pragma unroll
        for (int j = 0; j < 8; j++) UNPK2(lo[j], hi[j], acc[ip][j]);
        size_t base0 = (size_t)(by * 128 + ty * 8 + 2 * ip) * N + bx * 128 + tx * 8;
        size_t base1 = base0 + N;
        *(float4*)(C + base0)     = make_float4(lo[0], lo[1], lo[2], lo[3]);
        *(float4*)(C + base0 + 4) = make_float4(lo[4], lo[5], lo[6], lo[7]);
        *(float4*)(C + base1)     = make_float4(hi[0], hi[1], hi[2], hi[3]);
        *(float4*)(C + base1 + 4) = make_float4(hi[4], hi[5], hi[6], hi[7]);
    }
}

/* ------------------ node dots ------------------ */
__global__ void k_nodeDots1(const float* __restrict__ as1, const float* __restrict__ ad1) {
    int idx = blockIdx.x * blockDim.x + threadIdx.x;
    if (idx >= N_NODES * NHEADS) return;
    int n = idx >> 3, h = idx & 7;
    const float* hr = g_H1 + (size_t)n * INC + h * HIDC;
    float ss = 0.f, sd = 0.f;
    #pragma unroll 8
    for (int c = 0; c < HIDC; c++) { float v = hr[c]; ss += v * as1[h * HIDC + c]; sd += v * ad1[h * HIDC + c]; }
    g_aS[idx] = ss; g_aD[idx] = sd;
}

__global__ void k_nodeDots2(const float* __restrict__ as2, const float* __restrict__ ad2) {
    int n = (blockIdx.x * blockDim.x + threadIdx.x) >> 5;
    int lane = threadIdx.x & 31;
    if (n >= N_NODES) return;
    float ss = 0.f, sd = 0.f;
    for (int c = lane; c < OUTC; c += 32) {
        float v = g_G[(size_t)n * OUTC + c];
        ss += v * as2[c]; sd += v * ad2[c];
    }
    #pragma unroll
    for (int o = 16; o; o >>= 1) {
        ss += __shfl_down_sync(0xffffffffu, ss, o);
        sd += __shfl_down_sync(0xffffffffu, sd, o);
    }
    if (lane == 0) { g_aS[n] = ss; g_aD[n] = sd; }
}

/* ------------------ fused layer 1: softmax + aggregate per dst block ------------ */
__global__ void __launch_bounds__(256) k_fused1(const float* __restrict__ b1) {
    int d = blockIdx.x, tid = threadIdx.x, lane = tid & 31, w = tid >> 5;
    int begin = g_offGat[d], deg = g_offGat[d + 1] - begin;
    __shared__ float elS[CAP1][9], emS[CAP1][9];
    __shared__ int   sIdx[CAP1];
    __shared__ float mxs[2][8], sms[2][8];

    float aDd = g_aD[d * NHEADS + w];     /* warp w == head w */

    if (deg <= CAP1) {
        float m1 = -INFINITY, m2 = -INFINITY;
        for (int t = lane; t < deg; t += 32) {
            int e = g_listGat[begin + t];
            int s = srcOf(e);
            if (w == 0) sIdx[t] = s;
            float ev = g_aS[s * NHEADS + w] + aDd;
            float mw = g_mw[(size_t)s * N_NODES + d];
            float el = leaky(ev), em = leaky(ev * mw);
            elS[t][w] = el; emS[t][w] = em;
            m1 = fmaxf(m1, el); m2 = fmaxf(m2, em);
        }
        #pragma unroll
        for (int o = 16; o; o >>= 1) {
            m1 = fmaxf(m1, __shfl_down_sync(0xffffffffu, m1, o));
            m2 = fmaxf(m2, __shfl_down_sync(0xffffffffu, m2, o));
        }
        if (lane == 0) { mxs[0][w] = m1; mxs[1][w] = m2; }
        __syncthreads();
        float M1 = mxs[0][w], M2 = mxs[1][w];
        float s1 = 0.f, s2 = 0.f;
        for (int t = lane; t < deg; t += 32) {
            float a1 = expf(elS[t][w] - M1), a2 = expf(emS[t][w] - M2);
            elS[t][w] = a1; emS[t][w] = a2;
            s1 += a1; s2 += a2;
        }
        #pragma unroll
        for (int o = 16; o; o >>= 1) {
            s1 += __shfl_down_sync(0xffffffffu, s1, o);
            s2 += __shfl_down_sync(0xffffffffu, s2, o);
        }
        if (lane == 0) { sms[0][w] = s1; sms[1][w] = s2; }
        __syncthreads();
        float i1 = BETA_W / (sms[0][w] + 1e-16f);
        float i2 = (1.f - BETA_W) / (sms[1][w] + 1e-16f);
        for (int t = lane; t < deg; t += 32)
            elS[t][w] = elS[t][w] * i1 + emS[t][w] * i2;   /* alpha */
        __syncthreads();

        int hc0 = tid, hc1 = tid + 256;
        int h0 = hc0 >> 6, h1 = hc1 >> 6;
        float acc0 = 0.f, acc1 = 0.f;
        #pragma unroll 4
        for (int t = 0; t < deg; t++) {
            int s = sIdx[t];
            const float* hr = g_H1 + (size_t)s * INC;
            acc0 += elS[t][h0] * hr[hc0];
            acc1 += elS[t][h1] * hr[hc1];
        }
        float v0 = acc0 + b1[hc0];
        float v1 = acc1 + b1[hc1];
        g_H2[(size_t)d * INC + hc0] = v0 > 0.f ? v0 : expm1f(v0);
        g_H2[(size_t)d * INC + hc1] = v1 > 0.f ? v1 : expm1f(v1);
    } else {
        /* fallback: streaming recompute (rare/never for this dataset) */
        float m1 = -INFINITY, m2 = -INFINITY;
        for (int t = lane; t < deg; t += 32) {
            int e = g_listGat[begin + t];
            int s = srcOf(e);
            float ev = g_aS[s * NHEADS + w] + aDd;
            float mw = g_mw[(size_t)s * N_NODES + d];
            m1 = fmaxf(m1, leaky(ev)); m2 = fmaxf(m2, leaky(ev * mw));
        }
        #pragma unroll
        for (int o = 16; o; o >>= 1) {
            m1 = fmaxf(m1, __shfl_down_sync(0xffffffffu, m1, o));
            m2 = fmaxf(m2, __shfl_down_sync(0xffffffffu, m2, o));
        }
        if (lane == 0) { mxs[0][w] = m1; mxs[1][w] = m2; }
        __syncthreads();
        float M1 = mxs[0][w], M2 = mxs[1][w];
        float s1 = 0.f, s2 = 0.f;
        for (int t = lane; t < deg; t += 32) {
            int e = g_listGat[begin + t];
            int s = srcOf(e);
            float ev = g_aS[s * NHEADS + w] + aDd;
            float mw = g_mw[(size_t)s * N_NODES + d];
            s1 += expf(leaky(ev) - M1); s2 += expf(leaky(ev * mw) - M2);
        }
        #pragma unroll
        for (int o = 16; o; o >>= 1) {
            s1 += __shfl_down_sync(0xffffffffu, s1, o);
            s2 += __shfl_down_sync(0xffffffffu, s2, o);
        }
        if (lane == 0) { sms[0][w] = s1; sms[1][w] = s2; }
        __syncthreads();
        int hc0 = tid, hc1 = tid + 256;
        int h0 = hc0 >> 6, h1 = hc1 >> 6;
        float M10 = mxs[0][h0], M20 = mxs[1][h0], M11 = mxs[0][h1], M21 = mxs[1][h1];
        float i10 = BETA_W / (sms[0][h0] + 1e-16f), i20 = (1.f - BETA_W) / (sms[1][h0] + 1e-16f);
        float i11 = BETA_W / (sms[0][h1] + 1e-16f), i21 = (1.f - BETA_W) / (sms[1][h1] + 1e-16f);
        float aD0 = g_aD[d * NHEADS + h0], aD1 = g_aD[d * NHEADS + h1];
        float acc0 = 0.f, acc1 = 0.f;
        for (int t = 0; t < deg; t++) {
            int e = g_listGat[begin + t];
            int s = srcOf(e);
            float mw = g_mw[(size_t)s * N_NODES + d];
            float ev0 = g_aS[s * NHEADS + h0] + aD0;
            float ev1 = g_aS[s * NHEADS + h1] + aD1;
            float a0 = expf(leaky(ev0) - M10) * i10 + expf(leaky(ev0 * mw) - M20) * i20;
            float a1 = expf(leaky(ev1) - M11) * i11 + expf(leaky(ev1 * mw) - M21) * i21;
            const float* hr = g_H1 + (size_t)s * INC;
            acc0 += a0 * hr[hc0];
            acc1 += a1 * hr[hc1];
        }
        float v0 = acc0 + b1[hc0];
        float v1 = acc1 + b1[hc1];
        g_H2[(size_t)d * INC + hc0] = v0 > 0.f ? v0 : expm1f(v0);
        g_H2[(size_t)d * INC + hc1] = v1 > 0.f ? v1 : expm1f(v1);
    }
}

/* ------------------ fused layer 2 (1 head) ------------------ */
__global__ void __launch_bounds__(256) k_fused2(const float* __restrict__ b2,
                                                float* __restrict__ out) {
    int d = blockIdx.x, tid = threadIdx.x, lane = tid & 31, w = tid >> 5;
    int begin = g_offGat[d], deg = g_offGat[d + 1] - begin;
    __shared__ float elS[CAP2], emS[CAP2];
    __shared__ int   sIdx[CAP2];
    __shared__ float red[4][8];
    __shared__ float fin[4];

    float aDd = g_aD[d];

    if (deg <= CAP2) {
        float m1 = -INFINITY, m2 = -INFINITY;
        for (int t = tid; t < deg; t += 256) {
            int e = g_listGat[begin + t];
            int s = srcOf(e);
            sIdx[t] = s;
            float ev = g_aS[s] + aDd;
            float mw = g_mw[(size_t)s * N_NODES + d];
            float el = leaky(ev), em = leaky(ev * mw);
            elS[t] = el; emS[t] = em;
            m1 = fmaxf(m1, el); m2 = fmaxf(m2, em);
        }
        #pragma unroll
        for (int o = 16; o; o >>= 1) {
            m1 = fmaxf(m1, __shfl_down_sync(0xffffffffu, m1, o));
            m2 = fmaxf(m2, __shfl_down_sync(0xffffffffu, m2, o));
        }
        if (lane == 0) { red[0][w] = m1; red[1][w] = m2; }
        __syncthreads();
        if (tid == 0) {
            float a = -INFINITY, b = -INFINITY;
            #pragma unroll
            for (int i = 0; i < 8; i++) { a = fmaxf(a, red[0][i]); b = fmaxf(b, red[1][i]); }
            fin[0] = a; fin[1] = b;
        }
        __syncthreads();
        float M1 = fin[0], M2 = fin[1];
        float s1 = 0.f, s2 = 0.f;
        for (int t = tid; t < deg; t += 256) {
            float a1 = expf(elS[t] - M1), a2 = expf(emS[t] - M2);
            elS[t] = a1; emS[t] = a2;
            s1 += a1; s2 += a2;
        }
        #pragma unroll
        for (int o = 16; o; o >>= 1) {
            s1 += __shfl_down_sync(0xffffffffu, s1, o);
            s2 += __shfl_down_sync(0xffffffffu, s2, o);
        }
        if (lane == 0) { red[2][w] = s1; red[3][w] = s2; }
        __syncthreads();
        if (tid == 0) {
            float a = 0.f, b = 0.f;
            #pragma unroll
            for (int i = 0; i < 8; i++) { a += red[2][i]; b += red[3][i]; }
            fin[2] = a; fin[3] = b;
        }
        __syncthreads();
        float i1 = BETA_W / (fin[2] + 1e-16f), i2 = (1.f - BETA_W) / (fin[3] + 1e-16f);
        for (int t = tid; t < deg; t += 256)
            elS[t] = elS[t] * i1 + emS[t] * i2;   /* alpha */
        __syncthreads();

        int c = tid;
        float acc = 0.f;
        #pragma unroll 4
        for (int t = 0; t < deg; t++)
            acc += elS[t] * g_G[(size_t)sIdx[t] * OUTC + c];
        out[(size_t)d * OUTC + c] = acc + g_R[(size_t)d * OUTC + c] + b2[c];
    } else {
        /* streaming fallback */
        float m1 = -INFINITY, m2 = -INFINITY;
        for (int t = tid; t < deg; t += 256) {
            int e = g_listGat[begin + t];
            int s = srcOf(e);
            float ev = g_aS[s] + aDd;
            float mw = g_mw[(size_t)s * N_NODES + d];
            m1 = fmaxf(m1, leaky(ev)); m2 = fmaxf(m2, leaky(ev * mw));
        }
        #pragma unroll
        for (int o = 16; o; o >>= 1) {
            m1 = fmaxf(m1, __shfl_down_sync(0xffffffffu, m1, o));
            m2 = fmaxf(m2, __shfl_down_sync(0xffffffffu, m2, o));
        }
        if (lane == 0) { red[0][w] = m1; red[1][w] = m2; }
        __syncthreads();
        if (tid == 0) {
            float a = -INFINITY, b = -INFINITY;
            #pragma unroll
            for (int i = 0; i < 8; i++) { a = fmaxf(a, red[0][i]); b = fmaxf(b, red[1][i]); }
            fin[0] = a; fin[1] = b;
        }
        __syncthreads();
        float M1 = fin[0], M2 = fin[1];
        float s1 = 0.f, s2 = 0.f;
        for (int t = tid; t < deg; t += 256) {
            int e = g_listGat[begin + t];
            int s = srcOf(e);
            float ev = g_aS[s] + aDd;
            float mw = g_mw[(size_t)s * N_NODES + d];
            s1 += expf(leaky(ev) - M1); s2 += expf(leaky(ev * mw) - M2);
        }
        #pragma unroll
        for (int o = 16; o; o >>= 1) {
            s1 += __shfl_down_sync(0xffffffffu, s1, o);
            s2 += __shfl_down_sync(0xffffffffu, s2, o);
        }
        if (lane == 0) { red[2][w] = s1; red[3][w] = s2; }
        __syncthreads();
        if (tid == 0) {
            float a = 0.f, b = 0.f;
            #pragma unroll
            for (int i = 0; i < 8; i++) { a += red[2][i]; b += red[3][i]; }
            fin[2] = a; fin[3] = b;
        }
        __syncthreads();
        float i1 = BETA_W / (fin[2] + 1e-16f), i2 = (1.f - BETA_W) / (fin[3] + 1e-16f);
        int c = tid;
        float acc = 0.f;
        for (int t = 0; t < deg; t++) {
            int e = g_listGat[begin + t];
            int s = srcOf(e);
            float ev = g_aS[s] + aDd;
            float mw = g_mw[(size_t)s * N_NODES + d];
            float al = expf(leaky(ev) - M1) * i1 + expf(leaky(ev * mw) - M2) * i2;
            acc += al * g_G[(size_t)s * OUTC + c];
        }
        out[(size_t)d * OUTC + c] = acc + g_R[(size_t)d * OUTC + c] + b2[c];
    }
}

/* ------------------ launch ------------------ */
#define CDIV(a, b) (((a) + (b) - 1) / (b))

extern "C" void kernel_launch(void* const* d_in, const int* in_sizes, int n_in,
                              void* d_out, int out_size) {
    const float* x     = (const float*)d_in[0];
    const void*  ei    = d_in[1];
    const float* W1    = (const float*)d_in[2];
    const float* as1   = (const float*)d_in[3];
    const float* ad1   = (const float*)d_in[4];
    const float* b1    = (const float*)d_in[5];
    const float* W2    = (const float*)d_in[6];
    const float* as2   = (const float*)d_in[7];
    const float* ad2   = (const float*)d_in[8];
    const float* b2    = (const float*)d_in[9];
    const float* resW2 = (const float*)d_in[10];
    float*       out   = (float*)d_out;

    k_clearAll<<<2048, 256>>>();
    k_convert<<<CDIV(E_EDGES, 256), 256>>>(ei);
    k_fillAdj<<<CDIV(E_TOT, 256), 256>>>();
    k_rowCount<<<N_NODES, 256>>>();
    k_scanAll<<<3, 1024>>>();
    k_buildLists<<<CDIV(N_NODES * 32, 256), 256>>>();
    k_scatGat<<<CDIV(E_TOT, 256), 256>>>();
    k_motif<<<N_NODES, 256>>>();

    /* layer 1 */
    k_gemm<<<dim3(INC / 128, N_NODES / 128), 256>>>(x, 0, W1, nullptr, INC);
    k_nodeDots1<<<CDIV(N_NODES * NHEADS, 256), 256>>>(as1, ad1);
    k_fused1<<<N_NODES, 256>>>(b1);

    /* layer 2 */
    k_gemm<<<dim3(4, N_NODES / 128), 256>>>(nullptr, 1, W2, resW2, INC);
    k_nodeDots2<<<CDIV(N_NODES * 32, 256), 256>>>(as2, ad2);
    k_fused2<<<N_NODES, 256>>>(b2, out);
}

// round 17
// speedup vs baseline: 1.5303x; 1.0840x over previous
#include <cuda_runtime.h>
#include <math.h>

#define N_NODES 4096
#define E_EDGES 131072
#define E_TOT   (E_EDGES + N_NODES)
#define INC     512
#define HIDC    64
#define NHEADS  8
#define OUTC    256
#define BETA_W  0.5f
#define NSLOPE  0.2f
#define CAP1    320
#define CAP2    1024
#define NW      128            /* 32-bit words per adjacency row */

/* ------------------ device scratch ------------------ */
__device__ unsigned g_Abits[N_NODES * NW];                      /* 2MB bit adjacency */
__device__ __align__(16) float g_mw[(size_t)N_NODES * N_NODES]; /* motif weight (edge slots) */
__device__ int g_src[E_EDGES], g_dst[E_EDGES];
__device__ int g_cntOut[N_NODES], g_cntIn[N_NODES], g_cntGat[N_NODES];
__device__ int g_offOut[N_NODES + 1], g_offIn[N_NODES + 1], g_offGat[N_NODES + 1];
__device__ int g_curIn[N_NODES], g_curGat[N_NODES];
__device__ int g_listOut[E_TOT], g_listIn[E_TOT], g_listGat[E_TOT];
__device__ __align__(16) float g_H1[(size_t)N_NODES * INC];
__device__ __align__(16) float g_H2[(size_t)N_NODES * INC];
__device__ __align__(16) float g_G [(size_t)N_NODES * OUTC];
__device__ __align__(16) float g_R [(size_t)N_NODES * OUTC];
__device__ __align__(16) float g_aS[N_NODES * NHEADS], g_aD[N_NODES * NHEADS];

/* packed fp32x2 ops */
#define FMA2(d, a, b) asm("fma.rn.f32x2 %0, %1, %2, %0;" : "+l"(d) : "l"(a), "l"(b))
#define PACKDUP(d, f) asm("mov.b64 %0, {%1, %1};" : "=l"(d) : "f"(f))
#define UNPK2(lo, hi, v) asm("mov.b64 {%0, %1}, %2;" : "=f"(lo), "=f"(hi) : "l"(v))

__device__ __forceinline__ float leaky(float v) { return v > 0.f ? v : NSLOPE * v; }
__device__ __forceinline__ int srcOf(int e) { return (e < E_EDGES) ? g_src[e] : (e - E_EDGES); }
__device__ __forceinline__ int popc4(uint4 v) {
    return __popc(v.x) + __popc(v.y) + __popc(v.z) + __popc(v.w);
}

/* ------------------ clear + diagonal + counters (one pass, no race) ---------- */
__global__ void k_clearInit() {
    int w = blockIdx.x * blockDim.x + threadIdx.x;     /* grid covers 524288 words */
    if (w < N_NODES * NW) {
        int r = w >> 7, j = w & (NW - 1);
        g_Abits[w] = (j == (r >> 5)) ? (1u << (r & 31)) : 0u;   /* self-loop bit */
    }
    if (w < N_NODES) {
        g_cntOut[w] = 0; g_cntIn[w] = 0; g_cntGat[w] = 1;       /* 1 = self loop */
        g_curIn[w] = 0;  g_curGat[w] = 0;
    }
}

/* ------------------ canonicalize edges + set bits ------------------ */
__global__ void k_convEdges(const void* __restrict__ ei) {
    int e = blockIdx.x * blockDim.x + threadIdx.x;
    if (e >= E_EDGES) return;
    const unsigned* p = (const unsigned*)ei;
    int is64 = 1;
    #pragma unroll
    for (int i = 0; i < 8; i++) {
        unsigned lo = p[2 * i], hi = p[2 * i + 1];
        if (hi != 0u || lo >= (unsigned)N_NODES) { is64 = 0; break; }
    }
    int s, d;
    if (is64) {
        const long long* q = (const long long*)ei;
        s = (int)q[e]; d = (int)q[E_EDGES + e];
    } else {
        const int* q = (const int*)ei;
        s = q[e]; d = q[E_EDGES + e];
    }
    s &= (N_NODES - 1); d &= (N_NODES - 1);
    g_src[e] = s; g_dst[e] = d;
    atomicAdd(&g_cntGat[d], 1);
    atomicOr(&g_Abits[s * NW + (d >> 5)], 1u << (d & 31));
}

/* ------------------ row counts (popc) + column counts (atomics) -------------- */
__global__ void k_rowCnt() {
    int row  = (blockIdx.x * blockDim.x + threadIdx.x) >> 5;
    int lane = threadIdx.x & 31;
    if (row >= N_NODES) return;
    uint4 v = *(const uint4*)&g_Abits[row * NW + lane * 4];
    int c = popc4(v);
    unsigned ws[4] = {v.x, v.y, v.z, v.w};
    #pragma unroll
    for (int k = 0; k < 4; k++) {
        unsigned ww = ws[k];
        while (ww) {
            int b = __ffs(ww) - 1; ww &= ww - 1;
            atomicAdd(&g_cntIn[(lane * 4 + k) * 32 + b], 1);
        }
    }
    #pragma unroll
    for (int o = 16; o; o >>= 1) c += __shfl_down_sync(0xffffffffu, c, o);
    if (lane == 0) g_cntOut[row] = c;
}

/* 3 parallel scans: blockIdx.x = which */
__global__ void k_scanAll() {
    int which = blockIdx.x;
    const int* cnt = which == 0 ? g_cntOut : (which == 1 ? g_cntIn : g_cntGat);
    int*       off = which == 0 ? g_offOut : (which == 1 ? g_offIn : g_offGat);
    __shared__ int wsum[32];
    int tid = threadIdx.x, lane = tid & 31, wid = tid >> 5;
    int b = tid * 4;
    int c0 = cnt[b], c1 = cnt[b + 1], c2 = cnt[b + 2], c3 = cnt[b + 3];
    int tot = c0 + c1 + c2 + c3;
    int inc = tot;
    #pragma unroll
    for (int o = 1; o < 32; o <<= 1) {
        int n = __shfl_up_sync(0xffffffffu, inc, o);
        if (lane >= o) inc += n;
    }
    if (lane == 31) wsum[wid] = inc;
    __syncthreads();
    if (wid == 0) {
        int v = wsum[lane];
        #pragma unroll
        for (int o = 1; o < 32; o <<= 1) {
            int n = __shfl_up_sync(0xffffffffu, v, o);
            if (lane >= o) v += n;
        }
        wsum[lane] = v;
    }
    __syncthreads();
    int base = (wid > 0 ? wsum[wid - 1] : 0) + inc - tot;   /* exclusive prefix */
    off[b] = base; off[b + 1] = base + c0; off[b + 2] = base + c0 + c1;
    off[b + 3] = base + c0 + c1 + c2;
    if (tid == 0) off[N_NODES] = wsum[31];
}

/* build listOut/listIn (bit rows, 512 blocks) + scatGat (remaining blocks) */
#define BL_ROWBLK 512
__global__ void k_buildLists() {
    if (blockIdx.x < BL_ROWBLK) {
        int row  = blockIdx.x * 8 + (threadIdx.x >> 5);
        int lane = threadIdx.x & 31;
        uint4 v = *(const uint4*)&g_Abits[row * NW + lane * 4];
        int c = popc4(v);
        int inc = c;
        #pragma unroll
        for (int o = 1; o < 32; o <<= 1) {
            int n = __shfl_up_sync(0xffffffffu, inc, o);
            if (lane >= o) inc += n;
        }
        int pos = g_offOut[row] + inc - c;
        unsigned ws[4] = {v.x, v.y, v.z, v.w};
        #pragma unroll
        for (int k = 0; k < 4; k++) {
            unsigned ww = ws[k];
            while (ww) {
                int b = __ffs(ww) - 1; ww &= ww - 1;
                int col = (lane * 4 + k) * 32 + b;
                g_listOut[pos++] = col;
                int ip = atomicAdd(&g_curIn[col], 1);
                g_listIn[g_offIn[col] + ip] = row;
            }
        }
    } else {
        int e = (blockIdx.x - BL_ROWBLK) * 256 + threadIdx.x;
        if (e >= E_TOT) return;
        int d = (e < E_EDGES) ? g_dst[e] : (e - E_EDGES);
        int pos = atomicAdd(&g_curGat[d], 1);
        g_listGat[g_offGat[d] + pos] = e;
    }
}

/* ------------------ sparse motif ------------------ */
__global__ void k_motif() {
    int s = blockIdx.x;
    __shared__ float Brow[N_NODES];
    __shared__ float sRS;
    for (int j = threadIdx.x; j < N_NODES; j += blockDim.x) Brow[j] = 0.f;
    if (threadIdx.x == 0) sRS = 0.f;
    __syncthreads();

    int ob = g_offOut[s], oe = g_offOut[s + 1];
    for (int oi = ob + threadIdx.x; oi < oe; oi += blockDim.x) {
        int k = g_listOut[oi];
        int b = g_offOut[k], e2 = g_offOut[k + 1];
        for (int t = b; t < e2; t++) atomicAdd(&Brow[g_listOut[t]], 1.0f);
    }
    __syncthreads();

    float p = 0.f;
    for (int j = threadIdx.x; j < N_NODES; j += blockDim.x)
        p += Brow[j] * (float)(g_offOut[j + 1] - g_offOut[j]);
    atomicAdd(&sRS, p);
    __syncthreads();
    float rs = sRS; if (rs < 1.f) rs = 1.f;

    int lane = threadIdx.x & 31, w = threadIdx.x >> 5;
    int nw = blockDim.x >> 5;
    for (int oi = ob + w; oi < oe; oi += nw) {
        int dd = g_listOut[oi];
        int b = g_offIn[dd], e2 = g_offIn[dd + 1];
        float sum = 0.f;
        for (int t = b + lane; t < e2; t += 32) sum += Brow[g_listIn[t]];
        #pragma unroll
        for (int o = 16; o; o >>= 1) sum += __shfl_down_sync(0xffffffffu, sum, o);
        if (lane == 0) g_mw[(size_t)s * N_NODES + dd] = sum / rs;
    }
}

/* ------------------ f32x2 GEMM (128x128 tile, 8x8/thread) ------------------ */
__global__ void __launch_bounds__(256) k_gemm(const float* __restrict__ Aext, int mode,
                                              const float* __restrict__ B0,
                                              const float* __restrict__ B1, int K) {
    __shared__ __align__(16) float As[16][128];
    __shared__ __align__(16) float Bs[16][128];
    int tid = threadIdx.x;
    int bx = blockIdx.x, by = blockIdx.y;
    const float* A; const float* B; float* C; int N;
    if (mode == 0) { A = Aext; B = B0; C = g_H1; N = 512; }
    else {
        A = g_H2; N = 256;
        if (bx < 2) { B = B0; C = g_G; } else { B = B1; C = g_R; bx -= 2; }
    }
    int tx = tid & 15, ty = tid >> 4;
    int arow = tid >> 1, akoff = (tid & 1) * 8;
    int bk = tid >> 4, bnoff = (tid & 15) * 8;

    unsigned long long acc[4][8];
    #pragma unroll
    for (int i = 0; i < 4; i++)
        #pragma unroll
        for (int j = 0; j < 8; j++) acc[i][j] = 0ull;

    const float* Abase = A + (size_t)(by * 128 + arow) * K + akoff;
    const float* Bbase = B + (size_t)bk * N + bx * 128 + bnoff;

    for (int k0 = 0; k0 < K; k0 += 16) {
        float4 a0 = *(const float4*)(Abase + k0);
        float4 a1 = *(const float4*)(Abase + k0 + 4);
        As[akoff + 0][arow] = a0.x; As[akoff + 1][arow] = a0.y;
        As[akoff + 2][arow] = a0.z; As[akoff + 3][arow] = a0.w;
        As[akoff + 4][arow] = a1.x; As[akoff + 5][arow] = a1.y;
        As[akoff + 6][arow] = a1.z; As[akoff + 7][arow] = a1.w;
        const float* Bg = Bbase + (size_t)k0 * N;
        *(float4*)&Bs[bk][bnoff]     = *(const float4*)(Bg);
        *(float4*)&Bs[bk][bnoff + 4] = *(const float4*)(Bg + 4);
        __syncthreads();
        #pragma unroll
        for (int k = 0; k < 16; k++) {
            ulonglong2 aA = *(const ulonglong2*)&As[k][ty * 8];
            ulonglong2 aB = *(const ulonglong2*)&As[k][ty * 8 + 4];
            float4 bv0 = *(const float4*)&Bs[k][tx * 8];
            float4 bv1 = *(const float4*)&Bs[k][tx * 8 + 4];
            unsigned long long bb[8];
            PACKDUP(bb[0], bv0.x); PACKDUP(bb[1], bv0.y);
            PACKDUP(bb[2], bv0.z); PACKDUP(bb[3], bv0.w);
            PACKDUP(bb[4], bv1.x); PACKDUP(bb[5], bv1.y);
            PACKDUP(bb[6], bv1.z); PACKDUP(bb[7], bv1.w);
            unsigned long long aa0 = aA.x, aa1 = aA.y, aa2 = aB.x, aa3 = aB.y;
            #pragma unroll
            for (int j = 0; j < 8; j++) {
                FMA2(acc[0][j], aa0, bb[j]);
                FMA2(acc[1][j], aa1, bb[j]);
                FMA2(acc[2][j], aa2, bb[j]);
                FMA2(acc[3][j], aa3, bb[j]);
            }
        }
        __syncthreads();
    }
    #pragma unroll
    for (int ip = 0; ip < 4; ip++) {
        float lo[8], hi[8];
        #pragma unroll
        for (int j = 0; j < 8; j++) UNPK2(lo[j], hi[j], acc[ip][j]);
        size_t base0 = (size_t)(by * 128 + ty * 8 + 2 * ip) * N + bx * 128 + tx * 8;
        size_t base1 = base0 + N;
        *(float4*)(C + base0)     = make_float4(lo[0], lo[1], lo[2], lo[3]);
        *(float4*)(C + base0 + 4) = make_float4(lo[4], lo[5], lo[6], lo[7]);
        *(float4*)(C + base1)     = make_float4(hi[0], hi[1], hi[2], hi[3]);
        *(float4*)(C + base1 + 4) = make_float4(hi[4], hi[5], hi[6], hi[7]);
    }
}

/* ------------------ node dots ------------------ */
__global__ void k_nodeDots1(const float* __restrict__ as1, const float* __restrict__ ad1) {
    int idx = blockIdx.x * blockDim.x + threadIdx.x;
    if (idx >= N_NODES * NHEADS) return;
    int n = idx >> 3, h = idx & 7;
    const float* hr = g_H1 + (size_t)n * INC + h * HIDC;
    float ss = 0.f, sd = 0.f;
    #pragma unroll 8
    for (int c = 0; c < HIDC; c++) { float v = hr[c]; ss += v * as1[h * HIDC + c]; sd += v * ad1[h * HIDC + c]; }
    g_aS[idx] = ss; g_aD[idx] = sd;
}

__global__ void k_nodeDots2(const float* __restrict__ as2, const float* __restrict__ ad2) {
    int n = (blockIdx.x * blockDim.x + threadIdx.x) >> 5;
    int lane = threadIdx.x & 31;
    if (n >= N_NODES) return;
    float ss = 0.f, sd = 0.f;
    for (int c = lane; c < OUTC; c += 32) {
        float v = g_G[(size_t)n * OUTC + c];
        ss += v * as2[c]; sd += v * ad2[c];
    }
    #pragma unroll
    for (int o = 16; o; o >>= 1) {
        ss += __shfl_down_sync(0xffffffffu, ss, o);
        sd += __shfl_down_sync(0xffffffffu, sd, o);
    }
    if (lane == 0) { g_aS[n] = ss; g_aD[n] = sd; }
}

/* ------------------ fused layer 1 ------------------ */
__global__ void __launch_bounds__(256) k_fused1(const float* __restrict__ b1) {
    int d = blockIdx.x, tid = threadIdx.x, lane = tid & 31, w = tid >> 5;
    int begin = g_offGat[d], deg = g_offGat[d + 1] - begin;
    __shared__ float elS[CAP1][9], emS[CAP1][9];
    __shared__ int   sIdx[CAP1];
    __shared__ float mxs[2][8], sms[2][8];

    float aDd = g_aD[d * NHEADS + w];

    if (deg <= CAP1) {
        float m1 = -INFINITY, m2 = -INFINITY;
        for (int t = lane; t < deg; t += 32) {
            int e = g_listGat[begin + t];
            int s = srcOf(e);
            if (w == 0) sIdx[t] = s;
            float ev = g_aS[s * NHEADS + w] + aDd;
            float mw = g_mw[(size_t)s * N_NODES + d];
            float el = leaky(ev), em = leaky(ev * mw);
            elS[t][w] = el; emS[t][w] = em;
            m1 = fmaxf(m1, el); m2 = fmaxf(m2, em);
        }
        #pragma unroll
        for (int o = 16; o; o >>= 1) {
            m1 = fmaxf(m1, __shfl_down_sync(0xffffffffu, m1, o));
            m2 = fmaxf(m2, __shfl_down_sync(0xffffffffu, m2, o));
        }
        if (lane == 0) { mxs[0][w] = m1; mxs[1][w] = m2; }
        __syncthreads();
        float M1 = mxs[0][w], M2 = mxs[1][w];
        float s1 = 0.f, s2 = 0.f;
        for (int t = lane; t < deg; t += 32) {
            float a1 = expf(elS[t][w] - M1), a2 = expf(emS[t][w] - M2);
            elS[t][w] = a1; emS[t][w] = a2;
            s1 += a1; s2 += a2;
        }
        #pragma unroll
        for (int o = 16; o; o >>= 1) {
            s1 += __shfl_down_sync(0xffffffffu, s1, o);
            s2 += __shfl_down_sync(0xffffffffu, s2, o);
        }
        if (lane == 0) { sms[0][w] = s1; sms[1][w] = s2; }
        __syncthreads();
        float i1 = BETA_W / (sms[0][w] + 1e-16f);
        float i2 = (1.f - BETA_W) / (sms[1][w] + 1e-16f);
        for (int t = lane; t < deg; t += 32)
            elS[t][w] = elS[t][w] * i1 + emS[t][w] * i2;
        __syncthreads();

        int hc0 = tid, hc1 = tid + 256;
        int h0 = hc0 >> 6, h1 = hc1 >> 6;
        float acc0 = 0.f, acc1 = 0.f;
        #pragma unroll 4
        for (int t = 0; t < deg; t++) {
            int s = sIdx[t];
            const float* hr = g_H1 + (size_t)s * INC;
            acc0 += elS[t][h0] * hr[hc0];
            acc1 += elS[t][h1] * hr[hc1];
        }
        float v0 = acc0 + b1[hc0];
        float v1 = acc1 + b1[hc1];
        g_H2[(size_t)d * INC + hc0] = v0 > 0.f ? v0 : expm1f(v0);
        g_H2[(size_t)d * INC + hc1] = v1 > 0.f ? v1 : expm1f(v1);
    } else {
        float m1 = -INFINITY, m2 = -INFINITY;
        for (int t = lane; t < deg; t += 32) {
            int e = g_listGat[begin + t];
            int s = srcOf(e);
            float ev = g_aS[s * NHEADS + w] + aDd;
            float mw = g_mw[(size_t)s * N_NODES + d];
            m1 = fmaxf(m1, leaky(ev)); m2 = fmaxf(m2, leaky(ev * mw));
        }
        #pragma unroll
        for (int o = 16; o; o >>= 1) {
            m1 = fmaxf(m1, __shfl_down_sync(0xffffffffu, m1, o));
            m2 = fmaxf(m2, __shfl_down_sync(0xffffffffu, m2, o));
        }
        if (lane == 0) { mxs[0][w] = m1; mxs[1][w] = m2; }
        __syncthreads();
        float M1 = mxs[0][w], M2 = mxs[1][w];
        float s1 = 0.f, s2 = 0.f;
        for (int t = lane; t < deg; t += 32) {
            int e = g_listGat[begin + t];
            int s = srcOf(e);
            float ev = g_aS[s * NHEADS + w] + aDd;
            float mw = g_mw[(size_t)s * N_NODES + d];
            s1 += expf(leaky(ev) - M1); s2 += expf(leaky(ev * mw) - M2);
        }
        #pragma unroll
        for (int o = 16; o; o >>= 1) {
            s1 += __shfl_down_sync(0xffffffffu, s1, o);
            s2 += __shfl_down_sync(0xffffffffu, s2, o);
        }
        if (lane == 0) { sms[0][w] = s1; sms[1][w] = s2; }
        __syncthreads();
        int hc0 = tid, hc1 = tid + 256;
        int h0 = hc0 >> 6, h1 = hc1 >> 6;
        float M10 = mxs[0][h0], M20 = mxs[1][h0], M11 = mxs[0][h1], M21 = mxs[1][h1];
        float i10 = BETA_W / (sms[0][h0] + 1e-16f), i20 = (1.f - BETA_W) / (sms[1][h0] + 1e-16f);
        float i11 = BETA_W / (sms[0][h1] + 1e-16f), i21 = (1.f - BETA_W) / (sms[1][h1] + 1e-16f);
        float aD0 = g_aD[d * NHEADS + h0], aD1 = g_aD[d * NHEADS + h1];
        float acc0 = 0.f, acc1 = 0.f;
        for (int t = 0; t < deg; t++) {
            int e = g_listGat[begin + t];
            int s = srcOf(e);
            float mw = g_mw[(size_t)s * N_NODES + d];
            float ev0 = g_aS[s * NHEADS + h0] + aD0;
            float ev1 = g_aS[s * NHEADS + h1] + aD1;
            float a0 = expf(leaky(ev0) - M10) * i10 + expf(leaky(ev0 * mw) - M20) * i20;
            float a1 = expf(leaky(ev1) - M11) * i11 + expf(leaky(ev1 * mw) - M21) * i21;
            const float* hr = g_H1 + (size_t)s * INC;
            acc0 += a0 * hr[hc0];
            acc1 += a1 * hr[hc1];
        }
        float v0 = acc0 + b1[hc0];
        float v1 = acc1 + b1[hc1];
        g_H2[(size_t)d * INC + hc0] = v0 > 0.f ? v0 : expm1f(v0);
        g_H2[(size_t)d * INC + hc1] = v1 > 0.f ? v1 : expm1f(v1);
    }
}

/* ------------------ fused layer 2 ------------------ */
__global__ void __launch_bounds__(256) k_fused2(const float* __restrict__ b2,
                                                float* __restrict__ out) {
    int d = blockIdx.x, tid = threadIdx.x, lane = tid & 31, w = tid >> 5;
    int begin = g_offGat[d], deg = g_offGat[d + 1] - begin;
    __shared__ float elS[CAP2], emS[CAP2];
    __shared__ int   sIdx[CAP2];
    __shared__ float red[4][8];
    __shared__ float fin[4];

    float aDd = g_aD[d];

    if (deg <= CAP2) {
        float m1 = -INFINITY, m2 = -INFINITY;
        for (int t = tid; t < deg; t += 256) {
            int e = g_listGat[begin + t];
            int s = srcOf(e);
            sIdx[t] = s;
            float ev = g_aS[s] + aDd;
            float mw = g_mw[(size_t)s * N_NODES + d];
            float el = leaky(ev), em = leaky(ev * mw);
            elS[t] = el; emS[t] = em;
            m1 = fmaxf(m1, el); m2 = fmaxf(m2, em);
        }
        #pragma unroll
        for (int o = 16; o; o >>= 1) {
            m1 = fmaxf(m1, __shfl_down_sync(0xffffffffu, m1, o));
            m2 = fmaxf(m2, __shfl_down_sync(0xffffffffu, m2, o));
        }
        if (lane == 0) { red[0][w] = m1; red[1][w] = m2; }
        __syncthreads();
        if (tid == 0) {
            float a = -INFINITY, b = -INFINITY;
            #pragma unroll
            for (int i = 0; i < 8; i++) { a = fmaxf(a, red[0][i]); b = fmaxf(b, red[1][i]); }
            fin[0] = a; fin[1] = b;
        }
        __syncthreads();
        float M1 = fin[0], M2 = fin[1];
        float s1 = 0.f, s2 = 0.f;
        for (int t = tid; t < deg; t += 256) {
            float a1 = expf(elS[t] - M1), a2 = expf(emS[t] - M2);
            elS[t] = a1; emS[t] = a2;
            s1 += a1; s2 += a2;
        }
        #pragma unroll
        for (int o = 16; o; o >>= 1) {
            s1 += __shfl_down_sync(0xffffffffu, s1, o);
            s2 += __shfl_down_sync(0xffffffffu, s2, o);
        }
        if (lane == 0) { red[2][w] = s1; red[3][w] = s2; }
        __syncthreads();
        if (tid == 0) {
            float a = 0.f, b = 0.f;
            #pragma unroll
            for (int i = 0; i < 8; i++) { a += red[2][i]; b += red[3][i]; }
            fin[2] = a; fin[3] = b;
        }
        __syncthreads();
        float i1 = BETA_W / (fin[2] + 1e-16f), i2 = (1.f - BETA_W) / (fin[3] + 1e-16f);
        for (int t = tid; t < deg; t += 256)
            elS[t] = elS[t] * i1 + emS[t] * i2;
        __syncthreads();

        int c = tid;
        float acc = 0.f;
        #pragma unroll 4
        for (int t = 0; t < deg; t++)
            acc += elS[t] * g_G[(size_t)sIdx[t] * OUTC + c];
        out[(size_t)d * OUTC + c] = acc + g_R[(size_t)d * OUTC + c] + b2[c];
    } else {
        float m1 = -INFINITY, m2 = -INFINITY;
        for (int t = tid; t < deg; t += 256) {
            int e = g_listGat[begin + t];
            int s = srcOf(e);
            float ev = g_aS[s] + aDd;
            float mw = g_mw[(size_t)s * N_NODES + d];
            m1 = fmaxf(m1, leaky(ev)); m2 = fmaxf(m2, leaky(ev * mw));
        }
        #pragma unroll
        for (int o = 16; o; o >>= 1) {
            m1 = fmaxf(m1, __shfl_down_sync(0xffffffffu, m1, o));
            m2 = fmaxf(m2, __shfl_down_sync(0xffffffffu, m2, o));
        }
        if (lane == 0) { red[0][w] = m1; red[1][w] = m2; }
        __syncthreads();
        if (tid == 0) {
            float a = -INFINITY, b = -INFINITY;
            #pragma unroll
            for (int i = 0; i < 8; i++) { a = fmaxf(a, red[0][i]); b = fmaxf(b, red[1][i]); }
            fin[0] = a; fin[1] = b;
        }
        __syncthreads();
        float M1 = fin[0], M2 = fin[1];
        float s1 = 0.f, s2 = 0.f;
        for (int t = tid; t < deg; t += 256) {
            int e = g_listGat[begin + t];
            int s = srcOf(e);
            float ev = g_aS[s] + aDd;
            float mw = g_mw[(size_t)s * N_NODES + d];
            s1 += expf(leaky(ev) - M1); s2 += expf(leaky(ev * mw) - M2);
        }
        #pragma unroll
        for (int o = 16; o; o >>= 1) {
            s1 += __shfl_down_sync(0xffffffffu, s1, o);
            s2 += __shfl_down_sync(0xffffffffu, s2, o);
        }
        if (lane == 0) { red[2][w] = s1; red[3][w] = s2; }
        __syncthreads();
        if (tid == 0) {
            float a = 0.f, b = 0.f;
            #pragma unroll
            for (int i = 0; i < 8; i++) { a += red[2][i]; b += red[3][i]; }
            fin[2] = a; fin[3] = b;
        }
        __syncthreads();
        float i1 = BETA_W / (fin[2] + 1e-16f), i2 = (1.f - BETA_W) / (fin[3] + 1e-16f);
        int c = tid;
        float acc = 0.f;
        for (int t = 0; t < deg; t++) {
            int e = g_listGat[begin + t];
            int s = srcOf(e);
            float ev = g_aS[s] + aDd;
            float mw = g_mw[(size_t)s * N_NODES + d];
            float al = expf(leaky(ev) - M1) * i1 + expf(leaky(ev * mw) - M2) * i2;
            acc += al * g_G[(size_t)s * OUTC + c];
        }
        out[(size_t)d * OUTC + c] = acc + g_R[(size_t)d * OUTC + c] + b2[c];
    }
}

/* ------------------ launch ------------------ */
#define CDIV(a, b) (((a) + (b) - 1) / (b))

extern "C" void kernel_launch(void* const* d_in, const int* in_sizes, int n_in,
                              void* d_out, int out_size) {
    const float* x     = (const float*)d_in[0];
    const void*  ei    = d_in[1];
    const float* W1    = (const float*)d_in[2];
    const float* as1   = (const float*)d_in[3];
    const float* ad1   = (const float*)d_in[4];
    const float* b1    = (const float*)d_in[5];
    const float* W2    = (const float*)d_in[6];
    const float* as2   = (const float*)d_in[7];
    const float* ad2   = (const float*)d_in[8];
    const float* b2    = (const float*)d_in[9];
    const float* resW2 = (const float*)d_in[10];
    float*       out   = (float*)d_out;

    k_clearInit<<<CDIV(N_NODES * NW, 256), 256>>>();
    k_convEdges<<<CDIV(E_EDGES, 256), 256>>>(ei);
    k_rowCnt<<<CDIV(N_NODES * 32, 256), 256>>>();
    k_scanAll<<<3, 1024>>>();
    k_buildLists<<<BL_ROWBLK + CDIV(E_TOT, 256), 256>>>();
    k_motif<<<N_NODES, 256>>>();

    /* layer 1 */
    k_gemm<<<dim3(INC / 128, N_NODES / 128), 256>>>(x, 0, W1, nullptr, INC);
    k_nodeDots1<<<CDIV(N_NODES * NHEADS, 256), 256>>>(as1, ad1);
    k_fused1<<<N_NODES, 256>>>(b1);

    /* layer 2 */
    k_gemm<<<dim3(4, N_NODES / 128), 256>>>(nullptr, 1, W2, resW2, INC);
    k_nodeDots2<<<CDIV(N_NODES * 32, 256), 256>>>(as2, ad2);
    k_fused2<<<N_NODES, 256>>>(b2, out);
}